// round 13
// baseline (speedup 1.0000x reference)
#include <cuda_runtime.h>
#include <cuda_bf16.h>
#include <cstdint>

#define B_   64
#define T_   64
#define V_   32000
#define E_   512
#define H_   1024
#define G_   (3 * H_)
#define DI_  (E_ + H_)
#define MT_  (B_ * T_)
#define JC     8            // h-columns per CTA
#define NR     24           // gate rows per CTA (3*JC)
#define NCTA_R 128
#define RKC    64

// ---------------- scratch (device globals; no allocation) ----------------
__device__ float g_gx[MT_ * G_];
__device__ float g_ctxg[B_ * G_];
__device__ float g_hfin[B_ * H_];
__device__ int   g_didx[MT_];
__device__ int   g_bar;
__device__ __nv_bfloat16 g_hb[2][2][B_ * H_];
__device__ __nv_bfloat16 g_Ah[MT_ * H_];
__device__ __nv_bfloat16 g_Al[MT_ * H_];
__device__ __nv_bfloat16 g_Bh[(size_t)V_ * H_];
__device__ __nv_bfloat16 g_Bl[(size_t)V_ * H_];
__device__ __nv_bfloat16 g_WencH[NCTA_R * NR * H_];
__device__ __nv_bfloat16 g_WencL[NCTA_R * NR * H_];
__device__ __nv_bfloat16 g_WdecH[NCTA_R * NR * H_];
__device__ __nv_bfloat16 g_WdecL[NCTA_R * NR * H_];

// ================= base-ISA helpers =================
__device__ __forceinline__ uint32_t smem_u32(const void* p) {
    uint32_t a;
    asm("{ .reg .u64 t; cvta.to.shared.u64 t, %1; cvt.u32.u64 %0, t; }" : "=r"(a) : "l"(p));
    return a;
}
__device__ __forceinline__ void cpasync16(uint32_t saddr, const void* g) {
    asm volatile("cp.async.cg.shared.global [%0], [%1], 16;" :: "r"(saddr), "l"(g));
}
#define CP_COMMIT() asm volatile("cp.async.commit_group;" ::: "memory")
#define CP_WAIT1()  asm volatile("cp.async.wait_group 1;" ::: "memory")
#define CP_WAIT0()  asm volatile("cp.async.wait_group 0;" ::: "memory")
#define GBAR(id)    asm volatile("bar.sync %0, 256;" :: "r"(id) : "memory")

__device__ __forceinline__ void ldsm4(uint32_t* r, uint32_t addr) {
    asm volatile("ldmatrix.sync.aligned.m8n8.x4.shared.b16 {%0,%1,%2,%3}, [%4];"
                 : "=r"(r[0]), "=r"(r[1]), "=r"(r[2]), "=r"(r[3]) : "r"(addr));
}
__device__ __forceinline__ void ldsm2(uint32_t* r, uint32_t addr) {
    asm volatile("ldmatrix.sync.aligned.m8n8.x2.shared.b16 {%0,%1}, [%2];"
                 : "=r"(r[0]), "=r"(r[1]) : "r"(addr));
}
__device__ __forceinline__ void mma_bf16(float* d, const uint32_t* a, const uint32_t* b) {
    asm volatile(
        "mma.sync.aligned.m16n8k16.row.col.f32.bf16.bf16.f32 "
        "{%0,%1,%2,%3}, {%4,%5,%6,%7}, {%8,%9}, {%0,%1,%2,%3};"
        : "+f"(d[0]), "+f"(d[1]), "+f"(d[2]), "+f"(d[3])
        : "r"(a[0]), "r"(a[1]), "r"(a[2]), "r"(a[3]), "r"(b[0]), "r"(b[1]));
}
// release-arrive + acquire-poll grid barrier primitives
__device__ __forceinline__ void bar_arrive_release(int* p) {
    asm volatile("red.release.gpu.global.add.s32 [%0], 1;" :: "l"(p) : "memory");
}
// lane0-of-each-warp polls, then warp-converges: removes block-wide wake handoff
__device__ __forceinline__ void bar_wait_acquire_warp(const int* p, int target) {
    if ((threadIdx.x & 31) == 0) {
        int v;
        asm volatile("ld.global.acquire.gpu.b32 %0, [%1];" : "=r"(v) : "l"(p));
        while (v < target) {
            __nanosleep(64);
            asm volatile("ld.global.acquire.gpu.b32 %0, [%1];" : "=r"(v) : "l"(p));
        }
    }
    __syncwarp();
}

// ================= conversion kernels =================
__global__ __launch_bounds__(256) void split_bf16(
    const float* __restrict__ src, __nv_bfloat16* __restrict__ hi,
    __nv_bfloat16* __restrict__ lo, int n4)
{
    int i = blockIdx.x * 256 + threadIdx.x;
    if (i >= n4) return;
    float4 v = ((const float4*)src)[i];
    __nv_bfloat16 h0 = __float2bfloat16(v.x), h1 = __float2bfloat16(v.y);
    __nv_bfloat16 h2 = __float2bfloat16(v.z), h3 = __float2bfloat16(v.w);
    __nv_bfloat16 l0 = __float2bfloat16(v.x - __bfloat162float(h0));
    __nv_bfloat16 l1 = __float2bfloat16(v.y - __bfloat162float(h1));
    __nv_bfloat16 l2 = __float2bfloat16(v.z - __bfloat162float(h2));
    __nv_bfloat16 l3 = __float2bfloat16(v.w - __bfloat162float(h3));
    __nv_bfloat162* ph = (__nv_bfloat162*)hi;
    __nv_bfloat162* pl = (__nv_bfloat162*)lo;
    ph[2 * i]     = __nv_bfloat162(h0, h1);
    ph[2 * i + 1] = __nv_bfloat162(h2, h3);
    pl[2 * i]     = __nv_bfloat162(l0, l1);
    pl[2 * i + 1] = __nv_bfloat162(l2, l3);
}

__global__ __launch_bounds__(128) void gather_split(
    const float* __restrict__ emb, const int* __restrict__ idx,
    __nv_bfloat16* __restrict__ hi, __nv_bfloat16* __restrict__ lo)
{
    int m = blockIdx.x;
    const float* src = emb + (size_t)idx[m] * E_;
    int c = threadIdx.x;
    float4 v = ((const float4*)src)[c];
    __nv_bfloat16 h0 = __float2bfloat16(v.x), h1 = __float2bfloat16(v.y);
    __nv_bfloat16 h2 = __float2bfloat16(v.z), h3 = __float2bfloat16(v.w);
    __nv_bfloat16 l0 = __float2bfloat16(v.x - __bfloat162float(h0));
    __nv_bfloat16 l1 = __float2bfloat16(v.y - __bfloat162float(h1));
    __nv_bfloat16 l2 = __float2bfloat16(v.z - __bfloat162float(h2));
    __nv_bfloat16 l3 = __float2bfloat16(v.w - __bfloat162float(h3));
    size_t o = (size_t)m * E_ + c * 4;
    __nv_bfloat162* ph = (__nv_bfloat162*)(hi + o);
    __nv_bfloat162* pl = (__nv_bfloat162*)(lo + o);
    ph[0] = __nv_bfloat162(h0, h1); ph[1] = __nv_bfloat162(h2, h3);
    pl[0] = __nv_bfloat162(l0, l1); pl[1] = __nv_bfloat162(l2, l3);
}

__global__ __launch_bounds__(128) void split_stride(
    const float* __restrict__ src, int ld,
    __nv_bfloat16* __restrict__ hi, __nv_bfloat16* __restrict__ lo, int kd)
{
    int row = blockIdx.x;
    const float* s = src + (size_t)row * ld;
    for (int c = threadIdx.x; c < kd / 4; c += 128) {
        float4 v = ((const float4*)s)[c];
        __nv_bfloat16 h0 = __float2bfloat16(v.x), h1 = __float2bfloat16(v.y);
        __nv_bfloat16 h2 = __float2bfloat16(v.z), h3 = __float2bfloat16(v.w);
        __nv_bfloat16 l0 = __float2bfloat16(v.x - __bfloat162float(h0));
        __nv_bfloat16 l1 = __float2bfloat16(v.y - __bfloat162float(h1));
        __nv_bfloat16 l2 = __float2bfloat16(v.z - __bfloat162float(h2));
        __nv_bfloat16 l3 = __float2bfloat16(v.w - __bfloat162float(h3));
        size_t o = (size_t)row * kd + c * 4;
        __nv_bfloat162* ph = (__nv_bfloat162*)(hi + o);
        __nv_bfloat162* pl = (__nv_bfloat162*)(lo + o);
        ph[0] = __nv_bfloat162(h0, h1); ph[1] = __nv_bfloat162(h2, h3);
        pl[0] = __nv_bfloat162(l0, l1); pl[1] = __nv_bfloat162(l2, l3);
    }
}

// rearrange+split Whh for JC=8
__global__ __launch_bounds__(256) void whh_split(
    const float* __restrict__ W, __nv_bfloat16* __restrict__ hi,
    __nv_bfloat16* __restrict__ lo)
{
    int cta = blockIdx.x, l = blockIdx.y;
    int g = l >> 3, jj = l & 7;
    const float* s = W + (size_t)(g * H_ + cta * JC + jj) * H_;
    size_t drow = ((size_t)cta * NR + l) * H_;
    int c = threadIdx.x;
    float4 v = ((const float4*)s)[c];
    __nv_bfloat16 h0 = __float2bfloat16(v.x), h1 = __float2bfloat16(v.y);
    __nv_bfloat16 h2 = __float2bfloat16(v.z), h3 = __float2bfloat16(v.w);
    __nv_bfloat16 l0 = __float2bfloat16(v.x - __bfloat162float(h0));
    __nv_bfloat16 l1 = __float2bfloat16(v.y - __bfloat162float(h1));
    __nv_bfloat16 l2 = __float2bfloat16(v.z - __bfloat162float(h2));
    __nv_bfloat16 l3 = __float2bfloat16(v.w - __bfloat162float(h3));
    __nv_bfloat162* ph = (__nv_bfloat162*)(hi + drow + c * 4);
    __nv_bfloat162* pl = (__nv_bfloat162*)(lo + drow + c * 4);
    ph[0] = __nv_bfloat162(h0, h1); ph[1] = __nv_bfloat162(h2, h3);
    pl[0] = __nv_bfloat162(l0, l1); pl[1] = __nv_bfloat162(l2, l3);
}

__global__ void build_didx(const int* __restrict__ labels) {
    int m = blockIdx.x * 256 + threadIdx.x;
    if (m < MT_) {
        int t = m & (T_ - 1);
        g_didx[m] = (t == 0) ? 1 : labels[m - 1];
    }
}

// ================= HMMA NT GEMM 128x128, 3-stage single-sync pipeline =================
#define KCH 32
#define TILE_B  (128 * 64)
#define OFF_AH  0
#define OFF_AL  (TILE_B)
#define OFF_BH  (2 * TILE_B)
#define OFF_BL  (3 * TILE_B)
#define STAGE_B (4 * TILE_B)     // 32KB per stage

__device__ __forceinline__ uint32_t swz(int r, int c) {
    return (uint32_t)(r * 64 + ((c ^ ((r >> 1) & 3)) << 4));
}

template <int KD>
__global__ __launch_bounds__(256) void hmma_nt(
    const __nv_bfloat16* __restrict__ Ah, const __nv_bfloat16* __restrict__ Al,
    const __nv_bfloat16* __restrict__ Bh, const __nv_bfloat16* __restrict__ Bl,
    const float* __restrict__ bias, float* __restrict__ C, int ldc)
{
    constexpr int NST = KD / KCH;
    extern __shared__ char sm[];
    const uint32_t sb = smem_u32(sm);
    const int tid = threadIdx.x;
    const int lane = tid & 31;
    const int wid = tid >> 5;
    const int m0 = blockIdx.x * 128;
    const int n0 = blockIdx.y * 128;
    const int wm = wid >> 2;
    const int wn = wid & 3;

    const int r0 = tid >> 2, c0 = tid & 3;
    const int r1 = r0 + 64;
    const uint32_t so0 = swz(r0, c0);
    const uint32_t so1 = swz(r1, c0);
    const __nv_bfloat16* gAh0 = Ah + (size_t)(m0 + r0) * KD + c0 * 8;
    const __nv_bfloat16* gAh1 = Ah + (size_t)(m0 + r1) * KD + c0 * 8;
    const __nv_bfloat16* gAl0 = Al + (size_t)(m0 + r0) * KD + c0 * 8;
    const __nv_bfloat16* gAl1 = Al + (size_t)(m0 + r1) * KD + c0 * 8;
    const __nv_bfloat16* gBh0 = Bh + (size_t)(n0 + r0) * KD + c0 * 8;
    const __nv_bfloat16* gBh1 = Bh + (size_t)(n0 + r1) * KD + c0 * 8;
    const __nv_bfloat16* gBl0 = Bl + (size_t)(n0 + r0) * KD + c0 * 8;
    const __nv_bfloat16* gBl1 = Bl + (size_t)(n0 + r1) * KD + c0 * 8;

    int arow[4], axr[4];
#pragma unroll
    for (int mi = 0; mi < 4; mi++) {
        int r = wm * 64 + mi * 16 + (lane & 7) + ((lane >> 3) & 1) * 8;
        arow[mi] = r * 64;
        axr[mi] = (r >> 1) & 3;
    }
    const int acb = (lane >> 4);
    int brow[2], bxr[2];
#pragma unroll
    for (int nf2 = 0; nf2 < 2; nf2++) {
        int r = wn * 32 + nf2 * 16 + (lane & 7) + ((lane >> 4) & 1) * 8;
        brow[nf2] = r * 64;
        bxr[nf2] = (r >> 1) & 3;
    }
    const int bcb = ((lane >> 3) & 1);

    float acc[4][4][4];
#pragma unroll
    for (int mi = 0; mi < 4; mi++)
#pragma unroll
        for (int nf = 0; nf < 4; nf++)
#pragma unroll
            for (int q = 0; q < 4; q++) acc[mi][nf][q] = 0.f;

#define ISSUE(buf, kb) do { \
        uint32_t s_ = sb + (buf) * STAGE_B; \
        cpasync16(s_ + OFF_AH + so0, gAh0 + (kb)); cpasync16(s_ + OFF_AH + so1, gAh1 + (kb)); \
        cpasync16(s_ + OFF_AL + so0, gAl0 + (kb)); cpasync16(s_ + OFF_AL + so1, gAl1 + (kb)); \
        cpasync16(s_ + OFF_BH + so0, gBh0 + (kb)); cpasync16(s_ + OFF_BH + so1, gBh1 + (kb)); \
        cpasync16(s_ + OFF_BL + so0, gBl0 + (kb)); cpasync16(s_ + OFF_BL + so1, gBl1 + (kb)); \
    } while (0)

    ISSUE(0, 0);
    CP_COMMIT();
    ISSUE(1, KCH);
    CP_COMMIT();

    int buf = 0;
    for (int st = 0; st < NST; st++) {
        CP_WAIT1();
        __syncthreads();
        const uint32_t base = sb + (uint32_t)buf * STAGE_B;

#pragma unroll
        for (int s = 0; s < 2; s++) {
            uint32_t ah[4][4], al[4][4];
#pragma unroll
            for (int mi = 0; mi < 4; mi++) {
                uint32_t off = arow[mi] + ((((2 * s + acb)) ^ axr[mi]) << 4);
                ldsm4(ah[mi], base + OFF_AH + off);
                ldsm4(al[mi], base + OFF_AL + off);
            }
            uint32_t bhf[2][4], blf[2][4];
#pragma unroll
            for (int nf2 = 0; nf2 < 2; nf2++) {
                uint32_t off = brow[nf2] + ((((2 * s + bcb)) ^ bxr[nf2]) << 4);
                ldsm4(bhf[nf2], base + OFF_BH + off);
                ldsm4(blf[nf2], base + OFF_BL + off);
            }
#pragma unroll
            for (int mi = 0; mi < 4; mi++) {
#pragma unroll
                for (int nf = 0; nf < 4; nf++) {
                    const uint32_t* bp = &bhf[nf >> 1][(nf & 1) * 2];
                    const uint32_t* bq = &blf[nf >> 1][(nf & 1) * 2];
                    mma_bf16(acc[mi][nf], ah[mi], bp);
                    mma_bf16(acc[mi][nf], ah[mi], bq);
                    mma_bf16(acc[mi][nf], al[mi], bp);
                }
            }
        }
        if (st + 2 < NST) {
            int nbuf = buf + 2; if (nbuf >= 3) nbuf -= 3;
            ISSUE(nbuf, (st + 2) * KCH);
        }
        CP_COMMIT();
        if (++buf == 3) buf = 0;
    }
#undef ISSUE

    const int erow = m0 + wm * 64 + (lane >> 2);
    const int ecol0 = n0 + wn * 32 + (lane & 3) * 2;
#pragma unroll
    for (int mi = 0; mi < 4; mi++) {
#pragma unroll
        for (int nf = 0; nf < 4; nf++) {
            int col = ecol0 + nf * 8;
            float2 bv = *(const float2*)(bias + col);
            int row = erow + mi * 16;
            float2 o0 = make_float2(acc[mi][nf][0] + bv.x, acc[mi][nf][1] + bv.y);
            float2 o1 = make_float2(acc[mi][nf][2] + bv.x, acc[mi][nf][3] + bv.y);
            *(float2*)(C + (size_t)row * ldc + col) = o0;
            *(float2*)(C + (size_t)(row + 8) * ldc + col) = o1;
        }
    }
}

// ================= persistent fused GRU recurrence v6 =================
// 3 A-buffers/group, warp-scope barrier wake, early gx register loads.
#define WH_OFF  0
#define WL_OFF  49152
#define AB_OFF  98304                   // group g: +g*49152; buf b: +b*16384; lo +8192
#define SC_OFF  196608                  // 4 partials x 64x26 f32
#define HS_OFF  223232                  // 512 f32
#define BHB_OFF 225280                  // 24 f32 (pad)
#define CTX_OFF 225408                  // 64x24 f32
#define SMEM_REC 231552

__device__ __forceinline__ uint32_t rswz(int r, int c) {
    return (uint32_t)(r * 128 + ((c ^ (r & 7)) << 4));
}

template <bool DEC>
__global__ __launch_bounds__(512) void recur(
    const __nv_bfloat16* __restrict__ Wh, const __nv_bfloat16* __restrict__ Wl,
    const float* __restrict__ gx, const float* __restrict__ bhh,
    const float* __restrict__ ctxg, const float* __restrict__ dec_init)
{
    extern __shared__ char sm[];
    const uint32_t sb = smem_u32(sm);
    float* sC   = (float*)(sm + SC_OFF);
    float* h_s  = (float*)(sm + HS_OFF);
    float* bhhs = (float*)(sm + BHB_OFF);
    float* sctx = (float*)(sm + CTX_OFF);

    const int tid  = threadIdx.x;
    const int lane = tid & 31;
    const int wid  = tid >> 5;
    const int g    = wid >> 3;
    const int wm   = (wid >> 1) & 3;
    const int wh   = wid & 1;
    const int gtid = tid & 255;
    const int cta  = blockIdx.x;
    const int j0   = cta * JC;

    const __nv_bfloat16* wgh = Wh + (size_t)cta * NR * H_;
    const __nv_bfloat16* wgl = Wl + (size_t)cta * NR * H_;

    const int ar  = wm * 16 + (lane & 15);
    const int aca = lane >> 4;
    const int br_ = lane & 7;
    const int bca = (lane >> 3) & 1;

    // ---- load resident W ----
#pragma unroll
    for (int i = 0; i < 6; i++) {
        int v = tid + i * 512;
        int c = v / 192;
        int rem = v - c * 192;
        int r = rem >> 3, c8 = rem & 7;
        uint32_t so = rswz(r, c8);
        const size_t gsrc = (size_t)r * H_ + c * 64 + c8 * 8;
        cpasync16(sb + WH_OFF + c * 3072 + so, wgh + gsrc);
        cpasync16(sb + WL_OFF + c * 3072 + so, wgl + gsrc);
    }
    CP_COMMIT();

    if (tid < NR) bhhs[tid] = bhh[(tid >> 3) * H_ + j0 + (tid & 7)];
    const int gb = tid >> 3, gj = tid & 7;   // this thread's gate item
    {
        float h0 = DEC ? dec_init[j0 + gj] : 0.f;
        h_s[tid] = h0;
        __nv_bfloat16 hh = __float2bfloat16(h0);
        __nv_bfloat16 hl = __float2bfloat16(h0 - __bfloat162float(hh));
        g_hb[0][0][gb * H_ + j0 + gj] = hh;
        g_hb[0][1][gb * H_ + j0 + gj] = hl;
        if (DEC) {
            const float* cg = ctxg + (size_t)gb * G_;
            sctx[gb * 24 + gj]      = cg[j0 + gj];
            sctx[gb * 24 + 8 + gj]  = cg[H_ + j0 + gj];
            sctx[gb * 24 + 16 + gj] = cg[2 * H_ + j0 + gj];
        }
    }
    CP_WAIT0();
    __syncthreads();
    if (tid == 0) bar_arrive_release(&g_bar);
    bar_wait_acquire_warp(&g_bar, NCTA_R);

    for (int t = 0; t < T_; t++) {
        // ---- early gx loads for the gate (land during the kc loop) ----
        const float* gxm = gx + (size_t)(gb * T_ + t) * G_;
        float xr = gxm[j0 + gj];
        float xz = gxm[H_ + j0 + gj];
        float xn = gxm[2 * H_ + j0 + gj];

        const __nv_bfloat16 *pAh, *pAl;
        size_t astr;
        if (DEC) {
            if (t == 0) { pAh = g_hb[0][0]; pAl = g_hb[0][1]; astr = H_; }
            else {
                pAh = g_Ah + (size_t)(t - 1) * H_;
                pAl = g_Al + (size_t)(t - 1) * H_;
                astr = (size_t)T_ * H_;
            }
        } else {
            pAh = g_hb[t & 1][0]; pAl = g_hb[t & 1][1]; astr = H_;
        }

        auto rissue = [&](int buf, int chunk) {
            uint32_t s_ = sb + AB_OFF + (uint32_t)g * 49152u + (uint32_t)buf * 16384u;
            const __nv_bfloat16* ah = pAh + (size_t)chunk * RKC;
            const __nv_bfloat16* al = pAl + (size_t)chunk * RKC;
#pragma unroll
            for (int i_ = 0; i_ < 2; i_++) {
                int v_ = gtid + i_ * 256;
                int r_ = v_ >> 3, c8 = v_ & 7;
                uint32_t so_ = rswz(r_, c8);
                cpasync16(s_ + so_,         ah + (size_t)r_ * astr + c8 * 8);
                cpasync16(s_ + 8192u + so_, al + (size_t)r_ * astr + c8 * 8);
            }
        };

        float acc[3][4];
#pragma unroll
        for (int nt = 0; nt < 3; nt++)
#pragma unroll
            for (int q = 0; q < 4; q++) acc[nt][q] = 0.f;

        const int c0 = g * 8;
        rissue(0, c0);     CP_COMMIT();
        rissue(1, c0 + 1); CP_COMMIT();

        int buf = 0;
#pragma unroll 1
        for (int kc = 0; kc < 8; kc++) {
            CP_WAIT1();
            GBAR(1 + g);                 // buffer (kc-1)%3 vacated
            if (kc + 2 < 8) {
                int nbuf = buf + 2; if (nbuf >= 3) nbuf -= 3;
                rissue(nbuf, c0 + kc + 2);
            }
            CP_COMMIT();
            const uint32_t abase = sb + AB_OFF + (uint32_t)g * 49152u + (uint32_t)buf * 16384u;
            const uint32_t wch = (uint32_t)(c0 + kc) * 3072u;
#pragma unroll
            for (int ss = 0; ss < 2; ss++) {
                const int s = 2 * wh + ss;
                uint32_t aH[4], aL[4];
                uint32_t offA = (uint32_t)(ar * 128 + (((2 * s + aca) ^ (ar & 7)) << 4));
                ldsm4(aH, abase + offA);
                ldsm4(aL, abase + 8192u + offA);
#pragma unroll
                for (int nt = 0; nt < 3; nt++) {
                    int rb = nt * 8 + br_;
                    uint32_t offB = (uint32_t)(rb * 128 + (((2 * s + bca) ^ (rb & 7)) << 4));
                    uint32_t bH[2], bL[2];
                    ldsm2(bH, sb + WH_OFF + wch + offB);
                    ldsm2(bL, sb + WL_OFF + wch + offB);
                    mma_bf16(acc[nt], aH, bH);
                    mma_bf16(acc[nt], aH, bL);
                    mma_bf16(acc[nt], aL, bH);
                }
            }
            if (++buf == 3) buf = 0;
        }

        // stage k-partial gh to smem
        {
            float* sCp = sC + (g * 2 + wh) * 1664;
            int crow = wm * 16 + (lane >> 2);
            int ccol = (lane & 3) * 2;
#pragma unroll
            for (int nt = 0; nt < 3; nt++) {
                int cc = nt * 8 + ccol;
                *(float2*)&sCp[crow * 26 + cc]       = make_float2(acc[nt][0], acc[nt][1]);
                *(float2*)&sCp[(crow + 8) * 26 + cc] = make_float2(acc[nt][2], acc[nt][3]);
            }
        }
        __syncthreads();

        // gate: one item per thread (gx already in registers)
        {
            float ghr = bhhs[gj], ghz = bhhs[8 + gj], ghn = bhhs[16 + gj];
#pragma unroll
            for (int p = 0; p < 4; p++) {
                const float* sp = sC + p * 1664 + gb * 26;
                ghr += sp[gj];
                ghz += sp[8 + gj];
                ghn += sp[16 + gj];
            }
            if (DEC) {
                xr += sctx[gb * 24 + gj];
                xz += sctx[gb * 24 + 8 + gj];
                xn += sctx[gb * 24 + 16 + gj];
            }
            float r = 1.f / (1.f + expf(-(xr + ghr)));
            float z = 1.f / (1.f + expf(-(xz + ghz)));
            float n = tanhf(xn + r * ghn);
            float h2 = (1.f - z) * n + z * h_s[tid];
            h_s[tid] = h2;
            __nv_bfloat16 hh = __float2bfloat16(h2);
            __nv_bfloat16 hl = __float2bfloat16(h2 - __bfloat162float(hh));
            if (DEC) {
                size_t row = (size_t)(gb * T_ + t) * H_ + j0 + gj;
                g_Ah[row] = hh;
                g_Al[row] = hl;
            } else {
                int gc = gb * H_ + j0 + gj;
                g_hb[(t & 1) ^ 1][0][gc] = hh;
                g_hb[(t & 1) ^ 1][1][gc] = hl;
                if (t == T_ - 1) g_hfin[gc] = h2;
            }
        }
        __syncthreads();                 // all stores done before the release
        if (tid == 0) bar_arrive_release(&g_bar);
        bar_wait_acquire_warp(&g_bar, NCTA_R * (t + 2));
    }
}

// ---------------- small fp32 NT GEMM for ctxg ----------------
__global__ __launch_bounds__(128) void gemm64_nt(
    const float* __restrict__ A, int lda,
    const float* __restrict__ Bm, int ldb,
    float* __restrict__ C, int ldc, int klen)
{
    __shared__ float As[16][64];
    __shared__ float Bs[16][32];

    const int tid = threadIdx.x;
    const int tx = tid & 7;
    const int ty = tid >> 3;
    const int n0 = blockIdx.x * 32;

    const int am0 = tid >> 2;
    const int am1 = am0 + 32;
    const int ak  = (tid & 3) * 4;

    const float* Ar0 = A + (size_t)am0 * lda;
    const float* Ar1 = A + (size_t)am1 * lda;
    const float* Br  = Bm + (size_t)(n0 + am0) * ldb;

    float acc[4][4];
#pragma unroll
    for (int i = 0; i < 4; i++)
#pragma unroll
        for (int j = 0; j < 4; j++) acc[i][j] = 0.f;

    for (int k0 = 0; k0 < klen; k0 += 16) {
        float4 a0 = *(const float4*)(Ar0 + k0 + ak);
        float4 a1 = *(const float4*)(Ar1 + k0 + ak);
        float4 b  = *(const float4*)(Br  + k0 + ak);

        __syncthreads();
        As[ak + 0][am0] = a0.x; As[ak + 1][am0] = a0.y; As[ak + 2][am0] = a0.z; As[ak + 3][am0] = a0.w;
        As[ak + 0][am1] = a1.x; As[ak + 1][am1] = a1.y; As[ak + 2][am1] = a1.z; As[ak + 3][am1] = a1.w;
        Bs[ak + 0][am0] = b.x;  Bs[ak + 1][am0] = b.y;  Bs[ak + 2][am0] = b.z;  Bs[ak + 3][am0] = b.w;
        __syncthreads();

#pragma unroll
        for (int kk = 0; kk < 16; kk++) {
            float4 av = *(const float4*)&As[kk][ty * 4];
            float4 bv = *(const float4*)&Bs[kk][tx * 4];
            float a[4] = {av.x, av.y, av.z, av.w};
            float b4[4] = {bv.x, bv.y, bv.z, bv.w};
#pragma unroll
            for (int i = 0; i < 4; i++)
#pragma unroll
                for (int j = 0; j < 4; j++) acc[i][j] += a[i] * b4[j];
        }
    }

#pragma unroll
    for (int i = 0; i < 4; i++) {
        int m = ty * 4 + i;
        float* crow = C + (size_t)m * ldc + n0 + tx * 4;
        *(float4*)crow = make_float4(acc[i][0], acc[i][1], acc[i][2], acc[i][3]);
    }
}

// ---------------- launch ----------------
extern "C" void kernel_launch(void* const* d_in, const int* in_sizes, int n_in,
                              void* d_out, int out_size)
{
    const int*   x        = (const int*)d_in[0];
    const int*   labels   = (const int*)d_in[1];
    const float* enc_emb  = (const float*)d_in[2];
    const float* enc_Wih  = (const float*)d_in[3];
    const float* enc_Whh  = (const float*)d_in[4];
    const float* enc_bih  = (const float*)d_in[5];
    const float* enc_bhh  = (const float*)d_in[6];
    const float* dec_emb  = (const float*)d_in[7];
    const float* dec_Wih  = (const float*)d_in[8];
    const float* dec_Whh  = (const float*)d_in[9];
    const float* dec_bih  = (const float*)d_in[10];
    const float* dec_bhh  = (const float*)d_in[11];
    const float* dec_init = (const float*)d_in[12];
    const float* lin_W    = (const float*)d_in[13];
    const float* lin_b    = (const float*)d_in[14];
    float* out = (float*)d_out;

    float *gx, *ctxg, *hfin;
    int *didx, *bar;
    __nv_bfloat16 *pAh, *pAl, *pBh, *pBl, *weH, *weL, *wdH, *wdL;
    cudaGetSymbolAddress((void**)&gx, g_gx);
    cudaGetSymbolAddress((void**)&ctxg, g_ctxg);
    cudaGetSymbolAddress((void**)&hfin, g_hfin);
    cudaGetSymbolAddress((void**)&didx, g_didx);
    cudaGetSymbolAddress((void**)&bar, g_bar);
    cudaGetSymbolAddress((void**)&pAh, g_Ah);
    cudaGetSymbolAddress((void**)&pAl, g_Al);
    cudaGetSymbolAddress((void**)&pBh, g_Bh);
    cudaGetSymbolAddress((void**)&pBl, g_Bl);
    cudaGetSymbolAddress((void**)&weH, g_WencH);
    cudaGetSymbolAddress((void**)&weL, g_WencL);
    cudaGetSymbolAddress((void**)&wdH, g_WdecH);
    cudaGetSymbolAddress((void**)&wdL, g_WdecL);

    const int hmma_smem = 3 * STAGE_B;   // 96KB, 3-stage
    cudaFuncSetAttribute(hmma_nt<512>,  cudaFuncAttributeMaxDynamicSharedMemorySize, hmma_smem);
    cudaFuncSetAttribute(hmma_nt<1024>, cudaFuncAttributeMaxDynamicSharedMemorySize, hmma_smem);
    cudaFuncSetAttribute(recur<false>, cudaFuncAttributeMaxDynamicSharedMemorySize, SMEM_REC);
    cudaFuncSetAttribute(recur<true>,  cudaFuncAttributeMaxDynamicSharedMemorySize, SMEM_REC);

    // one-time weight conversions
    whh_split<<<dim3(NCTA_R, NR), 256>>>(enc_Whh, weH, weL);
    whh_split<<<dim3(NCTA_R, NR), 256>>>(dec_Whh, wdH, wdL);

    // encoder input gates
    split_stride<<<G_, 128>>>(enc_Wih, E_, pBh, pBl, E_);
    gather_split<<<MT_, 128>>>(enc_emb, x, pAh, pAl);
    hmma_nt<512><<<dim3(MT_ / 128, G_ / 128), 256, hmma_smem>>>(
        pAh, pAl, pBh, pBl, enc_bih, gx, G_);

    // encoder recurrence
    cudaMemsetAsync(bar, 0, sizeof(int));
    recur<false><<<NCTA_R, 512, SMEM_REC>>>(weH, weL, gx, enc_bhh, nullptr, nullptr);

    // ctx gate contribution
    gemm64_nt<<<G_ / 32, 128>>>(hfin, H_, dec_Wih + E_, DI_, ctxg, G_, H_);

    // decoder input gates
    build_didx<<<MT_ / 256, 256>>>(labels);
    gather_split<<<MT_, 128>>>(dec_emb, didx, pAh, pAl);
    split_stride<<<G_, 128>>>(dec_Wih, DI_, pBh, pBl, E_);
    hmma_nt<512><<<dim3(MT_ / 128, G_ / 128), 256, hmma_smem>>>(
        pAh, pAl, pBh, pBl, dec_bih, gx, G_);

    // decoder recurrence (writes bf16 hi/lo states directly into g_Ah/g_Al)
    cudaMemsetAsync(bar, 0, sizeof(int));
    recur<true><<<NCTA_R, 512, SMEM_REC>>>(wdH, wdL, gx, dec_bhh, ctxg, dec_init);

    // logits: 128x128 tile (2 CTAs/SM), 3-stage pipeline
    split_bf16<<<((int)((size_t)V_ * H_ / 4) + 255) / 256, 256>>>(
        lin_W, pBh, pBl, (int)((size_t)V_ * H_ / 4));
    hmma_nt<1024><<<dim3(MT_ / 128, V_ / 128), 256, hmma_smem>>>(
        pAh, pAl, pBh, pBl, lin_b, out, V_);
}

// round 14
// speedup vs baseline: 1.0906x; 1.0906x over previous
#include <cuda_runtime.h>
#include <cuda_bf16.h>
#include <cstdint>

#define B_   64
#define T_   64
#define V_   32000
#define E_   512
#define H_   1024
#define G_   (3 * H_)
#define DI_  (E_ + H_)
#define MT_  (B_ * T_)
#define JC     8            // h-columns per CTA
#define NR     24           // gate rows per CTA (3*JC)
#define NCTA_R 128
#define RKC    64

// ---------------- scratch (device globals; no allocation) ----------------
__device__ float g_gx[MT_ * G_];
__device__ float g_ctxg[B_ * G_];
__device__ float g_hfin[B_ * H_];
__device__ int   g_didx[MT_];
__device__ int   g_bar;
__device__ __nv_bfloat16 g_hb[2][2][B_ * H_];
__device__ __nv_bfloat16 g_Ah[MT_ * H_];
__device__ __nv_bfloat16 g_Al[MT_ * H_];
__device__ __nv_bfloat16 g_Bh[(size_t)V_ * H_];
__device__ __nv_bfloat16 g_Bl[(size_t)V_ * H_];
__device__ __nv_bfloat16 g_WencH[NCTA_R * NR * H_];
__device__ __nv_bfloat16 g_WencL[NCTA_R * NR * H_];
__device__ __nv_bfloat16 g_WdecH[NCTA_R * NR * H_];
__device__ __nv_bfloat16 g_WdecL[NCTA_R * NR * H_];

// ================= base-ISA helpers =================
__device__ __forceinline__ uint32_t smem_u32(const void* p) {
    uint32_t a;
    asm("{ .reg .u64 t; cvta.to.shared.u64 t, %1; cvt.u32.u64 %0, t; }" : "=r"(a) : "l"(p));
    return a;
}
__device__ __forceinline__ void cpasync16(uint32_t saddr, const void* g) {
    asm volatile("cp.async.cg.shared.global [%0], [%1], 16;" :: "r"(saddr), "l"(g));
}
#define CP_COMMIT() asm volatile("cp.async.commit_group;" ::: "memory")
#define CP_WAIT1()  asm volatile("cp.async.wait_group 1;" ::: "memory")
#define CP_WAIT0()  asm volatile("cp.async.wait_group 0;" ::: "memory")
#define GBAR(id)    asm volatile("bar.sync %0, 256;" :: "r"(id) : "memory")

__device__ __forceinline__ void ldsm4(uint32_t* r, uint32_t addr) {
    asm volatile("ldmatrix.sync.aligned.m8n8.x4.shared.b16 {%0,%1,%2,%3}, [%4];"
                 : "=r"(r[0]), "=r"(r[1]), "=r"(r[2]), "=r"(r[3]) : "r"(addr));
}
__device__ __forceinline__ void ldsm2(uint32_t* r, uint32_t addr) {
    asm volatile("ldmatrix.sync.aligned.m8n8.x2.shared.b16 {%0,%1}, [%2];"
                 : "=r"(r[0]), "=r"(r[1]) : "r"(addr));
}
__device__ __forceinline__ void mma_bf16(float* d, const uint32_t* a, const uint32_t* b) {
    asm volatile(
        "mma.sync.aligned.m16n8k16.row.col.f32.bf16.bf16.f32 "
        "{%0,%1,%2,%3}, {%4,%5,%6,%7}, {%8,%9}, {%0,%1,%2,%3};"
        : "+f"(d[0]), "+f"(d[1]), "+f"(d[2]), "+f"(d[3])
        : "r"(a[0]), "r"(a[1]), "r"(a[2]), "r"(a[3]), "r"(b[0]), "r"(b[1]));
}
// release-arrive + acquire-poll grid barrier primitives (ONE poller per CTA)
__device__ __forceinline__ void bar_arrive_release(int* p) {
    asm volatile("red.release.gpu.global.add.s32 [%0], 1;" :: "l"(p) : "memory");
}
__device__ __forceinline__ void bar_wait_acquire(const int* p, int target) {
    int v;
    asm volatile("ld.global.acquire.gpu.b32 %0, [%1];" : "=r"(v) : "l"(p));
    while (v < target) {
        __nanosleep(64);
        asm volatile("ld.global.acquire.gpu.b32 %0, [%1];" : "=r"(v) : "l"(p));
    }
}

// ================= conversion kernels =================
__global__ __launch_bounds__(256) void split_bf16(
    const float* __restrict__ src, __nv_bfloat16* __restrict__ hi,
    __nv_bfloat16* __restrict__ lo, int n4)
{
    int i = blockIdx.x * 256 + threadIdx.x;
    if (i >= n4) return;
    float4 v = ((const float4*)src)[i];
    __nv_bfloat16 h0 = __float2bfloat16(v.x), h1 = __float2bfloat16(v.y);
    __nv_bfloat16 h2 = __float2bfloat16(v.z), h3 = __float2bfloat16(v.w);
    __nv_bfloat16 l0 = __float2bfloat16(v.x - __bfloat162float(h0));
    __nv_bfloat16 l1 = __float2bfloat16(v.y - __bfloat162float(h1));
    __nv_bfloat16 l2 = __float2bfloat16(v.z - __bfloat162float(h2));
    __nv_bfloat16 l3 = __float2bfloat16(v.w - __bfloat162float(h3));
    __nv_bfloat162* ph = (__nv_bfloat162*)hi;
    __nv_bfloat162* pl = (__nv_bfloat162*)lo;
    ph[2 * i]     = __nv_bfloat162(h0, h1);
    ph[2 * i + 1] = __nv_bfloat162(h2, h3);
    pl[2 * i]     = __nv_bfloat162(l0, l1);
    pl[2 * i + 1] = __nv_bfloat162(l2, l3);
}

__global__ __launch_bounds__(128) void gather_split(
    const float* __restrict__ emb, const int* __restrict__ idx,
    __nv_bfloat16* __restrict__ hi, __nv_bfloat16* __restrict__ lo)
{
    int m = blockIdx.x;
    const float* src = emb + (size_t)idx[m] * E_;
    int c = threadIdx.x;
    float4 v = ((const float4*)src)[c];
    __nv_bfloat16 h0 = __float2bfloat16(v.x), h1 = __float2bfloat16(v.y);
    __nv_bfloat16 h2 = __float2bfloat16(v.z), h3 = __float2bfloat16(v.w);
    __nv_bfloat16 l0 = __float2bfloat16(v.x - __bfloat162float(h0));
    __nv_bfloat16 l1 = __float2bfloat16(v.y - __bfloat162float(h1));
    __nv_bfloat16 l2 = __float2bfloat16(v.z - __bfloat162float(h2));
    __nv_bfloat16 l3 = __float2bfloat16(v.w - __bfloat162float(h3));
    size_t o = (size_t)m * E_ + c * 4;
    __nv_bfloat162* ph = (__nv_bfloat162*)(hi + o);
    __nv_bfloat162* pl = (__nv_bfloat162*)(lo + o);
    ph[0] = __nv_bfloat162(h0, h1); ph[1] = __nv_bfloat162(h2, h3);
    pl[0] = __nv_bfloat162(l0, l1); pl[1] = __nv_bfloat162(l2, l3);
}

__global__ __launch_bounds__(128) void split_stride(
    const float* __restrict__ src, int ld,
    __nv_bfloat16* __restrict__ hi, __nv_bfloat16* __restrict__ lo, int kd)
{
    int row = blockIdx.x;
    const float* s = src + (size_t)row * ld;
    for (int c = threadIdx.x; c < kd / 4; c += 128) {
        float4 v = ((const float4*)s)[c];
        __nv_bfloat16 h0 = __float2bfloat16(v.x), h1 = __float2bfloat16(v.y);
        __nv_bfloat16 h2 = __float2bfloat16(v.z), h3 = __float2bfloat16(v.w);
        __nv_bfloat16 l0 = __float2bfloat16(v.x - __bfloat162float(h0));
        __nv_bfloat16 l1 = __float2bfloat16(v.y - __bfloat162float(h1));
        __nv_bfloat16 l2 = __float2bfloat16(v.z - __bfloat162float(h2));
        __nv_bfloat16 l3 = __float2bfloat16(v.w - __bfloat162float(h3));
        size_t o = (size_t)row * kd + c * 4;
        __nv_bfloat162* ph = (__nv_bfloat162*)(hi + o);
        __nv_bfloat162* pl = (__nv_bfloat162*)(lo + o);
        ph[0] = __nv_bfloat162(h0, h1); ph[1] = __nv_bfloat162(h2, h3);
        pl[0] = __nv_bfloat162(l0, l1); pl[1] = __nv_bfloat162(l2, l3);
    }
}

// rearrange+split Whh for JC=8
__global__ __launch_bounds__(256) void whh_split(
    const float* __restrict__ W, __nv_bfloat16* __restrict__ hi,
    __nv_bfloat16* __restrict__ lo)
{
    int cta = blockIdx.x, l = blockIdx.y;
    int g = l >> 3, jj = l & 7;
    const float* s = W + (size_t)(g * H_ + cta * JC + jj) * H_;
    size_t drow = ((size_t)cta * NR + l) * H_;
    int c = threadIdx.x;
    float4 v = ((const float4*)s)[c];
    __nv_bfloat16 h0 = __float2bfloat16(v.x), h1 = __float2bfloat16(v.y);
    __nv_bfloat16 h2 = __float2bfloat16(v.z), h3 = __float2bfloat16(v.w);
    __nv_bfloat16 l0 = __float2bfloat16(v.x - __bfloat162float(h0));
    __nv_bfloat16 l1 = __float2bfloat16(v.y - __bfloat162float(h1));
    __nv_bfloat16 l2 = __float2bfloat16(v.z - __bfloat162float(h2));
    __nv_bfloat16 l3 = __float2bfloat16(v.w - __bfloat162float(h3));
    __nv_bfloat162* ph = (__nv_bfloat162*)(hi + drow + c * 4);
    __nv_bfloat162* pl = (__nv_bfloat162*)(lo + drow + c * 4);
    ph[0] = __nv_bfloat162(h0, h1); ph[1] = __nv_bfloat162(h2, h3);
    pl[0] = __nv_bfloat162(l0, l1); pl[1] = __nv_bfloat162(l2, l3);
}

__global__ void build_didx(const int* __restrict__ labels) {
    int m = blockIdx.x * 256 + threadIdx.x;
    if (m < MT_) {
        int t = m & (T_ - 1);
        g_didx[m] = (t == 0) ? 1 : labels[m - 1];
    }
}

// ================= HMMA NT GEMM 128x128, 3-stage single-sync pipeline =================
#define KCH 32
#define TILE_B  (128 * 64)
#define OFF_AH  0
#define OFF_AL  (TILE_B)
#define OFF_BH  (2 * TILE_B)
#define OFF_BL  (3 * TILE_B)
#define STAGE_B (4 * TILE_B)     // 32KB per stage

__device__ __forceinline__ uint32_t swz(int r, int c) {
    return (uint32_t)(r * 64 + ((c ^ ((r >> 1) & 3)) << 4));
}

template <int KD>
__global__ __launch_bounds__(256) void hmma_nt(
    const __nv_bfloat16* __restrict__ Ah, const __nv_bfloat16* __restrict__ Al,
    const __nv_bfloat16* __restrict__ Bh, const __nv_bfloat16* __restrict__ Bl,
    const float* __restrict__ bias, float* __restrict__ C, int ldc)
{
    constexpr int NST = KD / KCH;
    extern __shared__ char sm[];
    const uint32_t sb = smem_u32(sm);
    const int tid = threadIdx.x;
    const int lane = tid & 31;
    const int wid = tid >> 5;
    const int m0 = blockIdx.x * 128;
    const int n0 = blockIdx.y * 128;
    const int wm = wid >> 2;
    const int wn = wid & 3;

    const int r0 = tid >> 2, c0 = tid & 3;
    const int r1 = r0 + 64;
    const uint32_t so0 = swz(r0, c0);
    const uint32_t so1 = swz(r1, c0);
    const __nv_bfloat16* gAh0 = Ah + (size_t)(m0 + r0) * KD + c0 * 8;
    const __nv_bfloat16* gAh1 = Ah + (size_t)(m0 + r1) * KD + c0 * 8;
    const __nv_bfloat16* gAl0 = Al + (size_t)(m0 + r0) * KD + c0 * 8;
    const __nv_bfloat16* gAl1 = Al + (size_t)(m0 + r1) * KD + c0 * 8;
    const __nv_bfloat16* gBh0 = Bh + (size_t)(n0 + r0) * KD + c0 * 8;
    const __nv_bfloat16* gBh1 = Bh + (size_t)(n0 + r1) * KD + c0 * 8;
    const __nv_bfloat16* gBl0 = Bl + (size_t)(n0 + r0) * KD + c0 * 8;
    const __nv_bfloat16* gBl1 = Bl + (size_t)(n0 + r1) * KD + c0 * 8;

    int arow[4], axr[4];
#pragma unroll
    for (int mi = 0; mi < 4; mi++) {
        int r = wm * 64 + mi * 16 + (lane & 7) + ((lane >> 3) & 1) * 8;
        arow[mi] = r * 64;
        axr[mi] = (r >> 1) & 3;
    }
    const int acb = (lane >> 4);
    int brow[2], bxr[2];
#pragma unroll
    for (int nf2 = 0; nf2 < 2; nf2++) {
        int r = wn * 32 + nf2 * 16 + (lane & 7) + ((lane >> 4) & 1) * 8;
        brow[nf2] = r * 64;
        bxr[nf2] = (r >> 1) & 3;
    }
    const int bcb = ((lane >> 3) & 1);

    float acc[4][4][4];
#pragma unroll
    for (int mi = 0; mi < 4; mi++)
#pragma unroll
        for (int nf = 0; nf < 4; nf++)
#pragma unroll
            for (int q = 0; q < 4; q++) acc[mi][nf][q] = 0.f;

#define ISSUE(buf, kb) do { \
        uint32_t s_ = sb + (buf) * STAGE_B; \
        cpasync16(s_ + OFF_AH + so0, gAh0 + (kb)); cpasync16(s_ + OFF_AH + so1, gAh1 + (kb)); \
        cpasync16(s_ + OFF_AL + so0, gAl0 + (kb)); cpasync16(s_ + OFF_AL + so1, gAl1 + (kb)); \
        cpasync16(s_ + OFF_BH + so0, gBh0 + (kb)); cpasync16(s_ + OFF_BH + so1, gBh1 + (kb)); \
        cpasync16(s_ + OFF_BL + so0, gBl0 + (kb)); cpasync16(s_ + OFF_BL + so1, gBl1 + (kb)); \
    } while (0)

    ISSUE(0, 0);
    CP_COMMIT();
    ISSUE(1, KCH);
    CP_COMMIT();

    int buf = 0;
    for (int st = 0; st < NST; st++) {
        CP_WAIT1();
        __syncthreads();
        const uint32_t base = sb + (uint32_t)buf * STAGE_B;

#pragma unroll
        for (int s = 0; s < 2; s++) {
            uint32_t ah[4][4], al[4][4];
#pragma unroll
            for (int mi = 0; mi < 4; mi++) {
                uint32_t off = arow[mi] + ((((2 * s + acb)) ^ axr[mi]) << 4);
                ldsm4(ah[mi], base + OFF_AH + off);
                ldsm4(al[mi], base + OFF_AL + off);
            }
            uint32_t bhf[2][4], blf[2][4];
#pragma unroll
            for (int nf2 = 0; nf2 < 2; nf2++) {
                uint32_t off = brow[nf2] + ((((2 * s + bcb)) ^ bxr[nf2]) << 4);
                ldsm4(bhf[nf2], base + OFF_BH + off);
                ldsm4(blf[nf2], base + OFF_BL + off);
            }
#pragma unroll
            for (int mi = 0; mi < 4; mi++) {
#pragma unroll
                for (int nf = 0; nf < 4; nf++) {
                    const uint32_t* bp = &bhf[nf >> 1][(nf & 1) * 2];
                    const uint32_t* bq = &blf[nf >> 1][(nf & 1) * 2];
                    mma_bf16(acc[mi][nf], ah[mi], bp);
                    mma_bf16(acc[mi][nf], ah[mi], bq);
                    mma_bf16(acc[mi][nf], al[mi], bp);
                }
            }
        }
        if (st + 2 < NST) {
            int nbuf = buf + 2; if (nbuf >= 3) nbuf -= 3;
            ISSUE(nbuf, (st + 2) * KCH);
        }
        CP_COMMIT();
        if (++buf == 3) buf = 0;
    }
#undef ISSUE

    const int erow = m0 + wm * 64 + (lane >> 2);
    const int ecol0 = n0 + wn * 32 + (lane & 3) * 2;
#pragma unroll
    for (int mi = 0; mi < 4; mi++) {
#pragma unroll
        for (int nf = 0; nf < 4; nf++) {
            int col = ecol0 + nf * 8;
            float2 bv = *(const float2*)(bias + col);
            int row = erow + mi * 16;
            float2 o0 = make_float2(acc[mi][nf][0] + bv.x, acc[mi][nf][1] + bv.y);
            float2 o1 = make_float2(acc[mi][nf][2] + bv.x, acc[mi][nf][3] + bv.y);
            *(float2*)(C + (size_t)row * ldc + col) = o0;
            *(float2*)(C + (size_t)(row + 8) * ldc + col) = o1;
        }
    }
}

// ================= persistent fused GRU recurrence v7 =================
// R12 structure (3 A-buffers, 1 named bar/chunk), tid0-poll barrier, early gx loads.
#define WH_OFF  0
#define WL_OFF  49152
#define AB_OFF  98304                   // group g: +g*49152; buf b: +b*16384; lo +8192
#define SC_OFF  196608                  // 4 partials x 64x26 f32
#define HS_OFF  223232                  // 512 f32
#define BHB_OFF 225280                  // 24 f32 (pad)
#define CTX_OFF 225408                  // 64x24 f32
#define SMEM_REC 231552

__device__ __forceinline__ uint32_t rswz(int r, int c) {
    return (uint32_t)(r * 128 + ((c ^ (r & 7)) << 4));
}

template <bool DEC>
__global__ __launch_bounds__(512) void recur(
    const __nv_bfloat16* __restrict__ Wh, const __nv_bfloat16* __restrict__ Wl,
    const float* __restrict__ gx, const float* __restrict__ bhh,
    const float* __restrict__ ctxg, const float* __restrict__ dec_init)
{
    extern __shared__ char sm[];
    const uint32_t sb = smem_u32(sm);
    float* sC   = (float*)(sm + SC_OFF);
    float* h_s  = (float*)(sm + HS_OFF);
    float* bhhs = (float*)(sm + BHB_OFF);
    float* sctx = (float*)(sm + CTX_OFF);

    const int tid  = threadIdx.x;
    const int lane = tid & 31;
    const int wid  = tid >> 5;
    const int g    = wid >> 3;
    const int wm   = (wid >> 1) & 3;
    const int wh   = wid & 1;
    const int gtid = tid & 255;
    const int cta  = blockIdx.x;
    const int j0   = cta * JC;

    const __nv_bfloat16* wgh = Wh + (size_t)cta * NR * H_;
    const __nv_bfloat16* wgl = Wl + (size_t)cta * NR * H_;

    const int ar  = wm * 16 + (lane & 15);
    const int aca = lane >> 4;
    const int br_ = lane & 7;
    const int bca = (lane >> 3) & 1;

    // ---- load resident W ----
#pragma unroll
    for (int i = 0; i < 6; i++) {
        int v = tid + i * 512;
        int c = v / 192;
        int rem = v - c * 192;
        int r = rem >> 3, c8 = rem & 7;
        uint32_t so = rswz(r, c8);
        const size_t gsrc = (size_t)r * H_ + c * 64 + c8 * 8;
        cpasync16(sb + WH_OFF + c * 3072 + so, wgh + gsrc);
        cpasync16(sb + WL_OFF + c * 3072 + so, wgl + gsrc);
    }
    CP_COMMIT();

    if (tid < NR) bhhs[tid] = bhh[(tid >> 3) * H_ + j0 + (tid & 7)];
    const int gb = tid >> 3, gj = tid & 7;   // this thread's gate item
    {
        float h0 = DEC ? dec_init[j0 + gj] : 0.f;
        h_s[tid] = h0;
        __nv_bfloat16 hh = __float2bfloat16(h0);
        __nv_bfloat16 hl = __float2bfloat16(h0 - __bfloat162float(hh));
        g_hb[0][0][gb * H_ + j0 + gj] = hh;
        g_hb[0][1][gb * H_ + j0 + gj] = hl;
        if (DEC) {
            const float* cg = ctxg + (size_t)gb * G_;
            sctx[gb * 24 + gj]      = cg[j0 + gj];
            sctx[gb * 24 + 8 + gj]  = cg[H_ + j0 + gj];
            sctx[gb * 24 + 16 + gj] = cg[2 * H_ + j0 + gj];
        }
    }
    CP_WAIT0();
    __syncthreads();
    if (tid == 0) {
        bar_arrive_release(&g_bar);
        bar_wait_acquire(&g_bar, NCTA_R);
    }
    __syncthreads();

    for (int t = 0; t < T_; t++) {
        // ---- early gx loads for the gate (land during the kc loop) ----
        const float* gxm = gx + (size_t)(gb * T_ + t) * G_;
        float xr = gxm[j0 + gj];
        float xz = gxm[H_ + j0 + gj];
        float xn = gxm[2 * H_ + j0 + gj];

        const __nv_bfloat16 *pAh, *pAl;
        size_t astr;
        if (DEC) {
            if (t == 0) { pAh = g_hb[0][0]; pAl = g_hb[0][1]; astr = H_; }
            else {
                pAh = g_Ah + (size_t)(t - 1) * H_;
                pAl = g_Al + (size_t)(t - 1) * H_;
                astr = (size_t)T_ * H_;
            }
        } else {
            pAh = g_hb[t & 1][0]; pAl = g_hb[t & 1][1]; astr = H_;
        }

        auto rissue = [&](int buf, int chunk) {
            uint32_t s_ = sb + AB_OFF + (uint32_t)g * 49152u + (uint32_t)buf * 16384u;
            const __nv_bfloat16* ah = pAh + (size_t)chunk * RKC;
            const __nv_bfloat16* al = pAl + (size_t)chunk * RKC;
#pragma unroll
            for (int i_ = 0; i_ < 2; i_++) {
                int v_ = gtid + i_ * 256;
                int r_ = v_ >> 3, c8 = v_ & 7;
                uint32_t so_ = rswz(r_, c8);
                cpasync16(s_ + so_,         ah + (size_t)r_ * astr + c8 * 8);
                cpasync16(s_ + 8192u + so_, al + (size_t)r_ * astr + c8 * 8);
            }
        };

        float acc[3][4];
#pragma unroll
        for (int nt = 0; nt < 3; nt++)
#pragma unroll
            for (int q = 0; q < 4; q++) acc[nt][q] = 0.f;

        const int c0 = g * 8;
        rissue(0, c0);     CP_COMMIT();
        rissue(1, c0 + 1); CP_COMMIT();

        int buf = 0;
#pragma unroll 1
        for (int kc = 0; kc < 8; kc++) {
            CP_WAIT1();
            GBAR(1 + g);                 // buffer (kc-1)%3 vacated
            if (kc + 2 < 8) {
                int nbuf = buf + 2; if (nbuf >= 3) nbuf -= 3;
                rissue(nbuf, c0 + kc + 2);
            }
            CP_COMMIT();
            const uint32_t abase = sb + AB_OFF + (uint32_t)g * 49152u + (uint32_t)buf * 16384u;
            const uint32_t wch = (uint32_t)(c0 + kc) * 3072u;
#pragma unroll
            for (int ss = 0; ss < 2; ss++) {
                const int s = 2 * wh + ss;
                uint32_t aH[4], aL[4];
                uint32_t offA = (uint32_t)(ar * 128 + (((2 * s + aca) ^ (ar & 7)) << 4));
                ldsm4(aH, abase + offA);
                ldsm4(aL, abase + 8192u + offA);
#pragma unroll
                for (int nt = 0; nt < 3; nt++) {
                    int rb = nt * 8 + br_;
                    uint32_t offB = (uint32_t)(rb * 128 + (((2 * s + bca) ^ (rb & 7)) << 4));
                    uint32_t bH[2], bL[2];
                    ldsm2(bH, sb + WH_OFF + wch + offB);
                    ldsm2(bL, sb + WL_OFF + wch + offB);
                    mma_bf16(acc[nt], aH, bH);
                    mma_bf16(acc[nt], aH, bL);
                    mma_bf16(acc[nt], aL, bH);
                }
            }
            if (++buf == 3) buf = 0;
        }

        // stage k-partial gh to smem
        {
            float* sCp = sC + (g * 2 + wh) * 1664;
            int crow = wm * 16 + (lane >> 2);
            int ccol = (lane & 3) * 2;
#pragma unroll
            for (int nt = 0; nt < 3; nt++) {
                int cc = nt * 8 + ccol;
                *(float2*)&sCp[crow * 26 + cc]       = make_float2(acc[nt][0], acc[nt][1]);
                *(float2*)&sCp[(crow + 8) * 26 + cc] = make_float2(acc[nt][2], acc[nt][3]);
            }
        }
        __syncthreads();

        // gate: one item per thread (gx already in registers)
        {
            float ghr = bhhs[gj], ghz = bhhs[8 + gj], ghn = bhhs[16 + gj];
#pragma unroll
            for (int p = 0; p < 4; p++) {
                const float* sp = sC + p * 1664 + gb * 26;
                ghr += sp[gj];
                ghz += sp[8 + gj];
                ghn += sp[16 + gj];
            }
            if (DEC) {
                xr += sctx[gb * 24 + gj];
                xz += sctx[gb * 24 + 8 + gj];
                xn += sctx[gb * 24 + 16 + gj];
            }
            float r = 1.f / (1.f + expf(-(xr + ghr)));
            float z = 1.f / (1.f + expf(-(xz + ghz)));
            float n = tanhf(xn + r * ghn);
            float h2 = (1.f - z) * n + z * h_s[tid];
            h_s[tid] = h2;
            __nv_bfloat16 hh = __float2bfloat16(h2);
            __nv_bfloat16 hl = __float2bfloat16(h2 - __bfloat162float(hh));
            if (DEC) {
                size_t row = (size_t)(gb * T_ + t) * H_ + j0 + gj;
                g_Ah[row] = hh;
                g_Al[row] = hl;
            } else {
                int gc = gb * H_ + j0 + gj;
                g_hb[(t & 1) ^ 1][0][gc] = hh;
                g_hb[(t & 1) ^ 1][1][gc] = hl;
                if (t == T_ - 1) g_hfin[gc] = h2;
            }
        }
        __syncthreads();
        if (tid == 0) {
            bar_arrive_release(&g_bar);
            bar_wait_acquire(&g_bar, NCTA_R * (t + 2));
        }
        __syncthreads();
    }
}

// ---------------- small fp32 NT GEMM for ctxg ----------------
__global__ __launch_bounds__(128) void gemm64_nt(
    const float* __restrict__ A, int lda,
    const float* __restrict__ Bm, int ldb,
    float* __restrict__ C, int ldc, int klen)
{
    __shared__ float As[16][64];
    __shared__ float Bs[16][32];

    const int tid = threadIdx.x;
    const int tx = tid & 7;
    const int ty = tid >> 3;
    const int n0 = blockIdx.x * 32;

    const int am0 = tid >> 2;
    const int am1 = am0 + 32;
    const int ak  = (tid & 3) * 4;

    const float* Ar0 = A + (size_t)am0 * lda;
    const float* Ar1 = A + (size_t)am1 * lda;
    const float* Br  = Bm + (size_t)(n0 + am0) * ldb;

    float acc[4][4];
#pragma unroll
    for (int i = 0; i < 4; i++)
#pragma unroll
        for (int j = 0; j < 4; j++) acc[i][j] = 0.f;

    for (int k0 = 0; k0 < klen; k0 += 16) {
        float4 a0 = *(const float4*)(Ar0 + k0 + ak);
        float4 a1 = *(const float4*)(Ar1 + k0 + ak);
        float4 b  = *(const float4*)(Br  + k0 + ak);

        __syncthreads();
        As[ak + 0][am0] = a0.x; As[ak + 1][am0] = a0.y; As[ak + 2][am0] = a0.z; As[ak + 3][am0] = a0.w;
        As[ak + 0][am1] = a1.x; As[ak + 1][am1] = a1.y; As[ak + 2][am1] = a1.z; As[ak + 3][am1] = a1.w;
        Bs[ak + 0][am0] = b.x;  Bs[ak + 1][am0] = b.y;  Bs[ak + 2][am0] = b.z;  Bs[ak + 3][am0] = b.w;
        __syncthreads();

#pragma unroll
        for (int kk = 0; kk < 16; kk++) {
            float4 av = *(const float4*)&As[kk][ty * 4];
            float4 bv = *(const float4*)&Bs[kk][tx * 4];
            float a[4] = {av.x, av.y, av.z, av.w};
            float b4[4] = {bv.x, bv.y, bv.z, bv.w};
#pragma unroll
            for (int i = 0; i < 4; i++)
#pragma unroll
                for (int j = 0; j < 4; j++) acc[i][j] += a[i] * b4[j];
        }
    }

#pragma unroll
    for (int i = 0; i < 4; i++) {
        int m = ty * 4 + i;
        float* crow = C + (size_t)m * ldc + n0 + tx * 4;
        *(float4*)crow = make_float4(acc[i][0], acc[i][1], acc[i][2], acc[i][3]);
    }
}

// ---------------- launch ----------------
extern "C" void kernel_launch(void* const* d_in, const int* in_sizes, int n_in,
                              void* d_out, int out_size)
{
    const int*   x        = (const int*)d_in[0];
    const int*   labels   = (const int*)d_in[1];
    const float* enc_emb  = (const float*)d_in[2];
    const float* enc_Wih  = (const float*)d_in[3];
    const float* enc_Whh  = (const float*)d_in[4];
    const float* enc_bih  = (const float*)d_in[5];
    const float* enc_bhh  = (const float*)d_in[6];
    const float* dec_emb  = (const float*)d_in[7];
    const float* dec_Wih  = (const float*)d_in[8];
    const float* dec_Whh  = (const float*)d_in[9];
    const float* dec_bih  = (const float*)d_in[10];
    const float* dec_bhh  = (const float*)d_in[11];
    const float* dec_init = (const float*)d_in[12];
    const float* lin_W    = (const float*)d_in[13];
    const float* lin_b    = (const float*)d_in[14];
    float* out = (float*)d_out;

    float *gx, *ctxg, *hfin;
    int *didx, *bar;
    __nv_bfloat16 *pAh, *pAl, *pBh, *pBl, *weH, *weL, *wdH, *wdL;
    cudaGetSymbolAddress((void**)&gx, g_gx);
    cudaGetSymbolAddress((void**)&ctxg, g_ctxg);
    cudaGetSymbolAddress((void**)&hfin, g_hfin);
    cudaGetSymbolAddress((void**)&didx, g_didx);
    cudaGetSymbolAddress((void**)&bar, g_bar);
    cudaGetSymbolAddress((void**)&pAh, g_Ah);
    cudaGetSymbolAddress((void**)&pAl, g_Al);
    cudaGetSymbolAddress((void**)&pBh, g_Bh);
    cudaGetSymbolAddress((void**)&pBl, g_Bl);
    cudaGetSymbolAddress((void**)&weH, g_WencH);
    cudaGetSymbolAddress((void**)&weL, g_WencL);
    cudaGetSymbolAddress((void**)&wdH, g_WdecH);
    cudaGetSymbolAddress((void**)&wdL, g_WdecL);

    const int hmma_smem = 3 * STAGE_B;   // 96KB, 3-stage
    cudaFuncSetAttribute(hmma_nt<512>,  cudaFuncAttributeMaxDynamicSharedMemorySize, hmma_smem);
    cudaFuncSetAttribute(hmma_nt<1024>, cudaFuncAttributeMaxDynamicSharedMemorySize, hmma_smem);
    cudaFuncSetAttribute(recur<false>, cudaFuncAttributeMaxDynamicSharedMemorySize, SMEM_REC);
    cudaFuncSetAttribute(recur<true>,  cudaFuncAttributeMaxDynamicSharedMemorySize, SMEM_REC);

    // one-time weight conversions
    whh_split<<<dim3(NCTA_R, NR), 256>>>(enc_Whh, weH, weL);
    whh_split<<<dim3(NCTA_R, NR), 256>>>(dec_Whh, wdH, wdL);

    // encoder input gates
    split_stride<<<G_, 128>>>(enc_Wih, E_, pBh, pBl, E_);
    gather_split<<<MT_, 128>>>(enc_emb, x, pAh, pAl);
    hmma_nt<512><<<dim3(MT_ / 128, G_ / 128), 256, hmma_smem>>>(
        pAh, pAl, pBh, pBl, enc_bih, gx, G_);

    // encoder recurrence
    cudaMemsetAsync(bar, 0, sizeof(int));
    recur<false><<<NCTA_R, 512, SMEM_REC>>>(weH, weL, gx, enc_bhh, nullptr, nullptr);

    // ctx gate contribution
    gemm64_nt<<<G_ / 32, 128>>>(hfin, H_, dec_Wih + E_, DI_, ctxg, G_, H_);

    // decoder input gates
    build_didx<<<MT_ / 256, 256>>>(labels);
    gather_split<<<MT_, 128>>>(dec_emb, didx, pAh, pAl);
    split_stride<<<G_, 128>>>(dec_Wih, DI_, pBh, pBl, E_);
    hmma_nt<512><<<dim3(MT_ / 128, G_ / 128), 256, hmma_smem>>>(
        pAh, pAl, pBh, pBl, dec_bih, gx, G_);

    // decoder recurrence (writes bf16 hi/lo states directly into g_Ah/g_Al)
    cudaMemsetAsync(bar, 0, sizeof(int));
    recur<true><<<NCTA_R, 512, SMEM_REC>>>(wdH, wdL, gx, dec_bhh, ctxg, dec_init);

    // logits: 128x128 tile (2 CTAs/SM), 3-stage pipeline
    split_bf16<<<((int)((size_t)V_ * H_ / 4) + 255) / 256, 256>>>(
        lin_W, pBh, pBl, (int)((size_t)V_ * H_ / 4));
    hmma_nt<1024><<<dim3(MT_ / 128, V_ / 128), 256, hmma_smem>>>(
        pAh, pAl, pBh, pBl, lin_b, out, V_);
}

// round 15
// speedup vs baseline: 1.1031x; 1.0115x over previous
#include <cuda_runtime.h>
#include <cuda_bf16.h>
#include <cstdint>

#define B_   64
#define T_   64
#define V_   32000
#define E_   512
#define H_   1024
#define G_   (3 * H_)
#define DI_  (E_ + H_)
#define MT_  (B_ * T_)
#define JC     8
#define NR     24
#define NCTA_R 128
#define RKC    64

// ---------------- scratch (device globals; no allocation) ----------------
__device__ float g_gx[MT_ * G_];
__device__ float g_ctxg[B_ * G_];
__device__ float g_hfin[B_ * H_];
__device__ int   g_didx[MT_];
__device__ int   g_bar;
__device__ __nv_bfloat16 g_hb[2][2][B_ * H_];
__device__ __nv_bfloat16 g_Ah[MT_ * H_];
__device__ __nv_bfloat16 g_Al[MT_ * H_];
__device__ __nv_bfloat16 g_Bh[(size_t)V_ * H_];
__device__ __nv_bfloat16 g_Bl[(size_t)V_ * H_];
__device__ __nv_bfloat16 g_WencH[NCTA_R * NR * H_];
__device__ __nv_bfloat16 g_WencL[NCTA_R * NR * H_];
__device__ __nv_bfloat16 g_WdecH[NCTA_R * NR * H_];
__device__ __nv_bfloat16 g_WdecL[NCTA_R * NR * H_];

// ================= base-ISA helpers =================
__device__ __forceinline__ uint32_t smem_u32(const void* p) {
    uint32_t a;
    asm("{ .reg .u64 t; cvta.to.shared.u64 t, %1; cvt.u32.u64 %0, t; }" : "=r"(a) : "l"(p));
    return a;
}
__device__ __forceinline__ void cpasync16(uint32_t saddr, const void* g) {
    asm volatile("cp.async.cg.shared.global [%0], [%1], 16;" :: "r"(saddr), "l"(g));
}
#define CP_COMMIT() asm volatile("cp.async.commit_group;" ::: "memory")
#define CP_WAIT1()  asm volatile("cp.async.wait_group 1;" ::: "memory")
#define CP_WAIT0()  asm volatile("cp.async.wait_group 0;" ::: "memory")
#define GBAR(id)    asm volatile("bar.sync %0, 256;" :: "r"(id) : "memory")

__device__ __forceinline__ void ldsm4(uint32_t* r, uint32_t addr) {
    asm volatile("ldmatrix.sync.aligned.m8n8.x4.shared.b16 {%0,%1,%2,%3}, [%4];"
                 : "=r"(r[0]), "=r"(r[1]), "=r"(r[2]), "=r"(r[3]) : "r"(addr));
}
__device__ __forceinline__ void ldsm2(uint32_t* r, uint32_t addr) {
    asm volatile("ldmatrix.sync.aligned.m8n8.x2.shared.b16 {%0,%1}, [%2];"
                 : "=r"(r[0]), "=r"(r[1]) : "r"(addr));
}
__device__ __forceinline__ void mma_bf16(float* d, const uint32_t* a, const uint32_t* b) {
    asm volatile(
        "mma.sync.aligned.m16n8k16.row.col.f32.bf16.bf16.f32 "
        "{%0,%1,%2,%3}, {%4,%5,%6,%7}, {%8,%9}, {%0,%1,%2,%3};"
        : "+f"(d[0]), "+f"(d[1]), "+f"(d[2]), "+f"(d[3])
        : "r"(a[0]), "r"(a[1]), "r"(a[2]), "r"(a[3]), "r"(b[0]), "r"(b[1]));
}
__device__ __forceinline__ void bar_arrive_release(int* p) {
    asm volatile("red.release.gpu.global.add.s32 [%0], 1;" :: "l"(p) : "memory");
}
__device__ __forceinline__ void bar_wait_acquire(const int* p, int target) {
    int v;
    asm volatile("ld.global.acquire.gpu.b32 %0, [%1];" : "=r"(v) : "l"(p));
    while (v < target) {
        __nanosleep(64);
        asm volatile("ld.global.acquire.gpu.b32 %0, [%1];" : "=r"(v) : "l"(p));
    }
}

// ================= conversion kernels =================
__global__ __launch_bounds__(256) void split_bf16(
    const float* __restrict__ src, __nv_bfloat16* __restrict__ hi,
    __nv_bfloat16* __restrict__ lo, int n4)
{
    int i = blockIdx.x * 256 + threadIdx.x;
    if (i >= n4) return;
    float4 v = ((const float4*)src)[i];
    __nv_bfloat16 h0 = __float2bfloat16(v.x), h1 = __float2bfloat16(v.y);
    __nv_bfloat16 h2 = __float2bfloat16(v.z), h3 = __float2bfloat16(v.w);
    __nv_bfloat16 l0 = __float2bfloat16(v.x - __bfloat162float(h0));
    __nv_bfloat16 l1 = __float2bfloat16(v.y - __bfloat162float(h1));
    __nv_bfloat16 l2 = __float2bfloat16(v.z - __bfloat162float(h2));
    __nv_bfloat16 l3 = __float2bfloat16(v.w - __bfloat162float(h3));
    __nv_bfloat162* ph = (__nv_bfloat162*)hi;
    __nv_bfloat162* pl = (__nv_bfloat162*)lo;
    ph[2 * i]     = __nv_bfloat162(h0, h1);
    ph[2 * i + 1] = __nv_bfloat162(h2, h3);
    pl[2 * i]     = __nv_bfloat162(l0, l1);
    pl[2 * i + 1] = __nv_bfloat162(l2, l3);
}

__global__ __launch_bounds__(128) void gather_split(
    const float* __restrict__ emb, const int* __restrict__ idx,
    __nv_bfloat16* __restrict__ hi, __nv_bfloat16* __restrict__ lo)
{
    int m = blockIdx.x;
    const float* src = emb + (size_t)idx[m] * E_;
    int c = threadIdx.x;
    float4 v = ((const float4*)src)[c];
    __nv_bfloat16 h0 = __float2bfloat16(v.x), h1 = __float2bfloat16(v.y);
    __nv_bfloat16 h2 = __float2bfloat16(v.z), h3 = __float2bfloat16(v.w);
    __nv_bfloat16 l0 = __float2bfloat16(v.x - __bfloat162float(h0));
    __nv_bfloat16 l1 = __float2bfloat16(v.y - __bfloat162float(h1));
    __nv_bfloat16 l2 = __float2bfloat16(v.z - __bfloat162float(h2));
    __nv_bfloat16 l3 = __float2bfloat16(v.w - __bfloat162float(h3));
    size_t o = (size_t)m * E_ + c * 4;
    __nv_bfloat162* ph = (__nv_bfloat162*)(hi + o);
    __nv_bfloat162* pl = (__nv_bfloat162*)(lo + o);
    ph[0] = __nv_bfloat162(h0, h1); ph[1] = __nv_bfloat162(h2, h3);
    pl[0] = __nv_bfloat162(l0, l1); pl[1] = __nv_bfloat162(l2, l3);
}

__global__ __launch_bounds__(128) void split_stride(
    const float* __restrict__ src, int ld,
    __nv_bfloat16* __restrict__ hi, __nv_bfloat16* __restrict__ lo, int kd)
{
    int row = blockIdx.x;
    const float* s = src + (size_t)row * ld;
    for (int c = threadIdx.x; c < kd / 4; c += 128) {
        float4 v = ((const float4*)s)[c];
        __nv_bfloat16 h0 = __float2bfloat16(v.x), h1 = __float2bfloat16(v.y);
        __nv_bfloat16 h2 = __float2bfloat16(v.z), h3 = __float2bfloat16(v.w);
        __nv_bfloat16 l0 = __float2bfloat16(v.x - __bfloat162float(h0));
        __nv_bfloat16 l1 = __float2bfloat16(v.y - __bfloat162float(h1));
        __nv_bfloat16 l2 = __float2bfloat16(v.z - __bfloat162float(h2));
        __nv_bfloat16 l3 = __float2bfloat16(v.w - __bfloat162float(h3));
        size_t o = (size_t)row * kd + c * 4;
        __nv_bfloat162* ph = (__nv_bfloat162*)(hi + o);
        __nv_bfloat162* pl = (__nv_bfloat162*)(lo + o);
        ph[0] = __nv_bfloat162(h0, h1); ph[1] = __nv_bfloat162(h2, h3);
        pl[0] = __nv_bfloat162(l0, l1); pl[1] = __nv_bfloat162(l2, l3);
    }
}

__global__ __launch_bounds__(256) void whh_split(
    const float* __restrict__ W, __nv_bfloat16* __restrict__ hi,
    __nv_bfloat16* __restrict__ lo)
{
    int cta = blockIdx.x, l = blockIdx.y;
    int g = l >> 3, jj = l & 7;
    const float* s = W + (size_t)(g * H_ + cta * JC + jj) * H_;
    size_t drow = ((size_t)cta * NR + l) * H_;
    int c = threadIdx.x;
    float4 v = ((const float4*)s)[c];
    __nv_bfloat16 h0 = __float2bfloat16(v.x), h1 = __float2bfloat16(v.y);
    __nv_bfloat16 h2 = __float2bfloat16(v.z), h3 = __float2bfloat16(v.w);
    __nv_bfloat16 l0 = __float2bfloat16(v.x - __bfloat162float(h0));
    __nv_bfloat16 l1 = __float2bfloat16(v.y - __bfloat162float(h1));
    __nv_bfloat16 l2 = __float2bfloat16(v.z - __bfloat162float(h2));
    __nv_bfloat16 l3 = __float2bfloat16(v.w - __bfloat162float(h3));
    __nv_bfloat162* ph = (__nv_bfloat162*)(hi + drow + c * 4);
    __nv_bfloat162* pl = (__nv_bfloat162*)(lo + drow + c * 4);
    ph[0] = __nv_bfloat162(h0, h1); ph[1] = __nv_bfloat162(h2, h3);
    pl[0] = __nv_bfloat162(l0, l1); pl[1] = __nv_bfloat162(l2, l3);
}

__global__ void build_didx(const int* __restrict__ labels) {
    int m = blockIdx.x * 256 + threadIdx.x;
    if (m < MT_) {
        int t = m & (T_ - 1);
        g_didx[m] = (t == 0) ? 1 : labels[m - 1];
    }
}

// ================= HMMA NT GEMM 128x128, 3-stage, FORCED 2 CTAs/SM =================
#define KCH 32
#define TILE_B  (128 * 64)
#define OFF_AH  0
#define OFF_AL  (TILE_B)
#define OFF_BH  (2 * TILE_B)
#define OFF_BL  (3 * TILE_B)
#define STAGE_B (4 * TILE_B)

__device__ __forceinline__ uint32_t swz(int r, int c) {
    return (uint32_t)(r * 64 + ((c ^ ((r >> 1) & 3)) << 4));
}

template <int KD>
__global__ __launch_bounds__(256, 2) void hmma_nt(
    const __nv_bfloat16* __restrict__ Ah, const __nv_bfloat16* __restrict__ Al,
    const __nv_bfloat16* __restrict__ Bh, const __nv_bfloat16* __restrict__ Bl,
    const float* __restrict__ bias, float* __restrict__ C, int ldc)
{
    constexpr int NST = KD / KCH;
    extern __shared__ char sm[];
    const uint32_t sb = smem_u32(sm);
    const int tid = threadIdx.x;
    const int lane = tid & 31;
    const int wid = tid >> 5;
    const int m0 = blockIdx.x * 128;
    const int n0 = blockIdx.y * 128;
    const int wm = wid >> 2;
    const int wn = wid & 3;

    const int r0 = tid >> 2, c0 = tid & 3;
    const int r1 = r0 + 64;
    const uint32_t so0 = swz(r0, c0);
    const uint32_t so1 = swz(r1, c0);
    const __nv_bfloat16* gAh0 = Ah + (size_t)(m0 + r0) * KD + c0 * 8;
    const __nv_bfloat16* gAh1 = Ah + (size_t)(m0 + r1) * KD + c0 * 8;
    const __nv_bfloat16* gAl0 = Al + (size_t)(m0 + r0) * KD + c0 * 8;
    const __nv_bfloat16* gAl1 = Al + (size_t)(m0 + r1) * KD + c0 * 8;
    const __nv_bfloat16* gBh0 = Bh + (size_t)(n0 + r0) * KD + c0 * 8;
    const __nv_bfloat16* gBh1 = Bh + (size_t)(n0 + r1) * KD + c0 * 8;
    const __nv_bfloat16* gBl0 = Bl + (size_t)(n0 + r0) * KD + c0 * 8;
    const __nv_bfloat16* gBl1 = Bl + (size_t)(n0 + r1) * KD + c0 * 8;

    int arow[4], axr[4];
#pragma unroll
    for (int mi = 0; mi < 4; mi++) {
        int r = wm * 64 + mi * 16 + (lane & 7) + ((lane >> 3) & 1) * 8;
        arow[mi] = r * 64;
        axr[mi] = (r >> 1) & 3;
    }
    const int acb = (lane >> 4);
    int brow[2], bxr[2];
#pragma unroll
    for (int nf2 = 0; nf2 < 2; nf2++) {
        int r = wn * 32 + nf2 * 16 + (lane & 7) + ((lane >> 4) & 1) * 8;
        brow[nf2] = r * 64;
        bxr[nf2] = (r >> 1) & 3;
    }
    const int bcb = ((lane >> 3) & 1);

    float acc[4][4][4];
#pragma unroll
    for (int mi = 0; mi < 4; mi++)
#pragma unroll
        for (int nf = 0; nf < 4; nf++)
#pragma unroll
            for (int q = 0; q < 4; q++) acc[mi][nf][q] = 0.f;

#define ISSUE(buf, kb) do { \
        uint32_t s_ = sb + (buf) * STAGE_B; \
        cpasync16(s_ + OFF_AH + so0, gAh0 + (kb)); cpasync16(s_ + OFF_AH + so1, gAh1 + (kb)); \
        cpasync16(s_ + OFF_AL + so0, gAl0 + (kb)); cpasync16(s_ + OFF_AL + so1, gAl1 + (kb)); \
        cpasync16(s_ + OFF_BH + so0, gBh0 + (kb)); cpasync16(s_ + OFF_BH + so1, gBh1 + (kb)); \
        cpasync16(s_ + OFF_BL + so0, gBl0 + (kb)); cpasync16(s_ + OFF_BL + so1, gBl1 + (kb)); \
    } while (0)

    ISSUE(0, 0);
    CP_COMMIT();
    ISSUE(1, KCH);
    CP_COMMIT();

    int buf = 0;
    for (int st = 0; st < NST; st++) {
        CP_WAIT1();
        __syncthreads();
        const uint32_t base = sb + (uint32_t)buf * STAGE_B;

#pragma unroll
        for (int s = 0; s < 2; s++) {
            uint32_t ah[4][4], al[4][4];
#pragma unroll
            for (int mi = 0; mi < 4; mi++) {
                uint32_t off = arow[mi] + ((((2 * s + acb)) ^ axr[mi]) << 4);
                ldsm4(ah[mi], base + OFF_AH + off);
                ldsm4(al[mi], base + OFF_AL + off);
            }
            uint32_t bhf[2][4], blf[2][4];
#pragma unroll
            for (int nf2 = 0; nf2 < 2; nf2++) {
                uint32_t off = brow[nf2] + ((((2 * s + bcb)) ^ bxr[nf2]) << 4);
                ldsm4(bhf[nf2], base + OFF_BH + off);
                ldsm4(blf[nf2], base + OFF_BL + off);
            }
#pragma unroll
            for (int mi = 0; mi < 4; mi++) {
#pragma unroll
                for (int nf = 0; nf < 4; nf++) {
                    const uint32_t* bp = &bhf[nf >> 1][(nf & 1) * 2];
                    const uint32_t* bq = &blf[nf >> 1][(nf & 1) * 2];
                    mma_bf16(acc[mi][nf], ah[mi], bp);
                    mma_bf16(acc[mi][nf], ah[mi], bq);
                    mma_bf16(acc[mi][nf], al[mi], bp);
                }
            }
        }
        if (st + 2 < NST) {
            int nbuf = buf + 2; if (nbuf >= 3) nbuf -= 3;
            ISSUE(nbuf, (st + 2) * KCH);
        }
        CP_COMMIT();
        if (++buf == 3) buf = 0;
    }
#undef ISSUE

    const int erow = m0 + wm * 64 + (lane >> 2);
    const int ecol0 = n0 + wn * 32 + (lane & 3) * 2;
#pragma unroll
    for (int mi = 0; mi < 4; mi++) {
#pragma unroll
        for (int nf = 0; nf < 4; nf++) {
            int col = ecol0 + nf * 8;
            float2 bv = *(const float2*)(bias + col);
            int row = erow + mi * 16;
            float2 o0 = make_float2(acc[mi][nf][0] + bv.x, acc[mi][nf][1] + bv.y);
            float2 o1 = make_float2(acc[mi][nf][2] + bv.x, acc[mi][nf][3] + bv.y);
            *(float2*)(C + (size_t)row * ldc + col) = o0;
            *(float2*)(C + (size_t)(row + 8) * ldc + col) = o1;
        }
    }
}

// ================= persistent fused GRU recurrence (R14) =================
#define WH_OFF  0
#define WL_OFF  49152
#define AB_OFF  98304
#define SC_OFF  196608
#define HS_OFF  223232
#define BHB_OFF 225280
#define CTX_OFF 225408
#define SMEM_REC 231552

__device__ __forceinline__ uint32_t rswz(int r, int c) {
    return (uint32_t)(r * 128 + ((c ^ (r & 7)) << 4));
}

template <bool DEC>
__global__ __launch_bounds__(512) void recur(
    const __nv_bfloat16* __restrict__ Wh, const __nv_bfloat16* __restrict__ Wl,
    const float* __restrict__ gx, const float* __restrict__ bhh,
    const float* __restrict__ ctxg, const float* __restrict__ dec_init)
{
    extern __shared__ char sm[];
    const uint32_t sb = smem_u32(sm);
    float* sC   = (float*)(sm + SC_OFF);
    float* h_s  = (float*)(sm + HS_OFF);
    float* bhhs = (float*)(sm + BHB_OFF);
    float* sctx = (float*)(sm + CTX_OFF);

    const int tid  = threadIdx.x;
    const int lane = tid & 31;
    const int wid  = tid >> 5;
    const int g    = wid >> 3;
    const int wm   = (wid >> 1) & 3;
    const int wh   = wid & 1;
    const int gtid = tid & 255;
    const int cta  = blockIdx.x;
    const int j0   = cta * JC;

    const __nv_bfloat16* wgh = Wh + (size_t)cta * NR * H_;
    const __nv_bfloat16* wgl = Wl + (size_t)cta * NR * H_;

    const int ar  = wm * 16 + (lane & 15);
    const int aca = lane >> 4;
    const int br_ = lane & 7;
    const int bca = (lane >> 3) & 1;

#pragma unroll
    for (int i = 0; i < 6; i++) {
        int v = tid + i * 512;
        int c = v / 192;
        int rem = v - c * 192;
        int r = rem >> 3, c8 = rem & 7;
        uint32_t so = rswz(r, c8);
        const size_t gsrc = (size_t)r * H_ + c * 64 + c8 * 8;
        cpasync16(sb + WH_OFF + c * 3072 + so, wgh + gsrc);
        cpasync16(sb + WL_OFF + c * 3072 + so, wgl + gsrc);
    }
    CP_COMMIT();

    if (tid < NR) bhhs[tid] = bhh[(tid >> 3) * H_ + j0 + (tid & 7)];
    const int gb = tid >> 3, gj = tid & 7;
    {
        float h0 = DEC ? dec_init[j0 + gj] : 0.f;
        h_s[tid] = h0;
        __nv_bfloat16 hh = __float2bfloat16(h0);
        __nv_bfloat16 hl = __float2bfloat16(h0 - __bfloat162float(hh));
        g_hb[0][0][gb * H_ + j0 + gj] = hh;
        g_hb[0][1][gb * H_ + j0 + gj] = hl;
        if (DEC) {
            const float* cg = ctxg + (size_t)gb * G_;
            sctx[gb * 24 + gj]      = cg[j0 + gj];
            sctx[gb * 24 + 8 + gj]  = cg[H_ + j0 + gj];
            sctx[gb * 24 + 16 + gj] = cg[2 * H_ + j0 + gj];
        }
    }
    CP_WAIT0();
    __syncthreads();
    if (tid == 0) {
        bar_arrive_release(&g_bar);
        bar_wait_acquire(&g_bar, NCTA_R);
    }
    __syncthreads();

    for (int t = 0; t < T_; t++) {
        const float* gxm = gx + (size_t)(gb * T_ + t) * G_;
        float xr = gxm[j0 + gj];
        float xz = gxm[H_ + j0 + gj];
        float xn = gxm[2 * H_ + j0 + gj];

        const __nv_bfloat16 *pAh, *pAl;
        size_t astr;
        if (DEC) {
            if (t == 0) { pAh = g_hb[0][0]; pAl = g_hb[0][1]; astr = H_; }
            else {
                pAh = g_Ah + (size_t)(t - 1) * H_;
                pAl = g_Al + (size_t)(t - 1) * H_;
                astr = (size_t)T_ * H_;
            }
        } else {
            pAh = g_hb[t & 1][0]; pAl = g_hb[t & 1][1]; astr = H_;
        }

        auto rissue = [&](int buf, int chunk) {
            uint32_t s_ = sb + AB_OFF + (uint32_t)g * 49152u + (uint32_t)buf * 16384u;
            const __nv_bfloat16* ah = pAh + (size_t)chunk * RKC;
            const __nv_bfloat16* al = pAl + (size_t)chunk * RKC;
#pragma unroll
            for (int i_ = 0; i_ < 2; i_++) {
                int v_ = gtid + i_ * 256;
                int r_ = v_ >> 3, c8 = v_ & 7;
                uint32_t so_ = rswz(r_, c8);
                cpasync16(s_ + so_,         ah + (size_t)r_ * astr + c8 * 8);
                cpasync16(s_ + 8192u + so_, al + (size_t)r_ * astr + c8 * 8);
            }
        };

        float acc[3][4];
#pragma unroll
        for (int nt = 0; nt < 3; nt++)
#pragma unroll
            for (int q = 0; q < 4; q++) acc[nt][q] = 0.f;

        const int c0 = g * 8;
        rissue(0, c0);     CP_COMMIT();
        rissue(1, c0 + 1); CP_COMMIT();

        int buf = 0;
#pragma unroll 1
        for (int kc = 0; kc < 8; kc++) {
            CP_WAIT1();
            GBAR(1 + g);
            if (kc + 2 < 8) {
                int nbuf = buf + 2; if (nbuf >= 3) nbuf -= 3;
                rissue(nbuf, c0 + kc + 2);
            }
            CP_COMMIT();
            const uint32_t abase = sb + AB_OFF + (uint32_t)g * 49152u + (uint32_t)buf * 16384u;
            const uint32_t wch = (uint32_t)(c0 + kc) * 3072u;
#pragma unroll
            for (int ss = 0; ss < 2; ss++) {
                const int s = 2 * wh + ss;
                uint32_t aH[4], aL[4];
                uint32_t offA = (uint32_t)(ar * 128 + (((2 * s + aca) ^ (ar & 7)) << 4));
                ldsm4(aH, abase + offA);
                ldsm4(aL, abase + 8192u + offA);
#pragma unroll
                for (int nt = 0; nt < 3; nt++) {
                    int rb = nt * 8 + br_;
                    uint32_t offB = (uint32_t)(rb * 128 + (((2 * s + bca) ^ (rb & 7)) << 4));
                    uint32_t bH[2], bL[2];
                    ldsm2(bH, sb + WH_OFF + wch + offB);
                    ldsm2(bL, sb + WL_OFF + wch + offB);
                    mma_bf16(acc[nt], aH, bH);
                    mma_bf16(acc[nt], aH, bL);
                    mma_bf16(acc[nt], aL, bH);
                }
            }
            if (++buf == 3) buf = 0;
        }

        {
            float* sCp = sC + (g * 2 + wh) * 1664;
            int crow = wm * 16 + (lane >> 2);
            int ccol = (lane & 3) * 2;
#pragma unroll
            for (int nt = 0; nt < 3; nt++) {
                int cc = nt * 8 + ccol;
                *(float2*)&sCp[crow * 26 + cc]       = make_float2(acc[nt][0], acc[nt][1]);
                *(float2*)&sCp[(crow + 8) * 26 + cc] = make_float2(acc[nt][2], acc[nt][3]);
            }
        }
        __syncthreads();

        {
            float ghr = bhhs[gj], ghz = bhhs[8 + gj], ghn = bhhs[16 + gj];
#pragma unroll
            for (int p = 0; p < 4; p++) {
                const float* sp = sC + p * 1664 + gb * 26;
                ghr += sp[gj];
                ghz += sp[8 + gj];
                ghn += sp[16 + gj];
            }
            if (DEC) {
                xr += sctx[gb * 24 + gj];
                xz += sctx[gb * 24 + 8 + gj];
                xn += sctx[gb * 24 + 16 + gj];
            }
            float r = 1.f / (1.f + expf(-(xr + ghr)));
            float z = 1.f / (1.f + expf(-(xz + ghz)));
            float n = tanhf(xn + r * ghn);
            float h2 = (1.f - z) * n + z * h_s[tid];
            h_s[tid] = h2;
            __nv_bfloat16 hh = __float2bfloat16(h2);
            __nv_bfloat16 hl = __float2bfloat16(h2 - __bfloat162float(hh));
            if (DEC) {
                size_t row = (size_t)(gb * T_ + t) * H_ + j0 + gj;
                g_Ah[row] = hh;
                g_Al[row] = hl;
            } else {
                int gc = gb * H_ + j0 + gj;
                g_hb[(t & 1) ^ 1][0][gc] = hh;
                g_hb[(t & 1) ^ 1][1][gc] = hl;
                if (t == T_ - 1) g_hfin[gc] = h2;
            }
        }
        __syncthreads();
        if (tid == 0) {
            bar_arrive_release(&g_bar);
            bar_wait_acquire(&g_bar, NCTA_R * (t + 2));
        }
        __syncthreads();
    }
}

// ---------------- small fp32 NT GEMM for ctxg ----------------
__global__ __launch_bounds__(128) void gemm64_nt(
    const float* __restrict__ A, int lda,
    const float* __restrict__ Bm, int ldb,
    float* __restrict__ C, int ldc, int klen)
{
    __shared__ float As[16][64];
    __shared__ float Bs[16][32];

    const int tid = threadIdx.x;
    const int tx = tid & 7;
    const int ty = tid >> 3;
    const int n0 = blockIdx.x * 32;

    const int am0 = tid >> 2;
    const int am1 = am0 + 32;
    const int ak  = (tid & 3) * 4;

    const float* Ar0 = A + (size_t)am0 * lda;
    const float* Ar1 = A + (size_t)am1 * lda;
    const float* Br  = Bm + (size_t)(n0 + am0) * ldb;

    float acc[4][4];
#pragma unroll
    for (int i = 0; i < 4; i++)
#pragma unroll
        for (int j = 0; j < 4; j++) acc[i][j] = 0.f;

    for (int k0 = 0; k0 < klen; k0 += 16) {
        float4 a0 = *(const float4*)(Ar0 + k0 + ak);
        float4 a1 = *(const float4*)(Ar1 + k0 + ak);
        float4 b  = *(const float4*)(Br  + k0 + ak);

        __syncthreads();
        As[ak + 0][am0] = a0.x; As[ak + 1][am0] = a0.y; As[ak + 2][am0] = a0.z; As[ak + 3][am0] = a0.w;
        As[ak + 0][am1] = a1.x; As[ak + 1][am1] = a1.y; As[ak + 2][am1] = a1.z; As[ak + 3][am1] = a1.w;
        Bs[ak + 0][am0] = b.x;  Bs[ak + 1][am0] = b.y;  Bs[ak + 2][am0] = b.z;  Bs[ak + 3][am0] = b.w;
        __syncthreads();

#pragma unroll
        for (int kk = 0; kk < 16; kk++) {
            float4 av = *(const float4*)&As[kk][ty * 4];
            float4 bv = *(const float4*)&Bs[kk][tx * 4];
            float a[4] = {av.x, av.y, av.z, av.w};
            float b4[4] = {bv.x, bv.y, bv.z, bv.w};
#pragma unroll
            for (int i = 0; i < 4; i++)
#pragma unroll
                for (int j = 0; j < 4; j++) acc[i][j] += a[i] * b4[j];
        }
    }

#pragma unroll
    for (int i = 0; i < 4; i++) {
        int m = ty * 4 + i;
        float* crow = C + (size_t)m * ldc + n0 + tx * 4;
        *(float4*)crow = make_float4(acc[i][0], acc[i][1], acc[i][2], acc[i][3]);
    }
}

// ---------------- launch ----------------
extern "C" void kernel_launch(void* const* d_in, const int* in_sizes, int n_in,
                              void* d_out, int out_size)
{
    const int*   x        = (const int*)d_in[0];
    const int*   labels   = (const int*)d_in[1];
    const float* enc_emb  = (const float*)d_in[2];
    const float* enc_Wih  = (const float*)d_in[3];
    const float* enc_Whh  = (const float*)d_in[4];
    const float* enc_bih  = (const float*)d_in[5];
    const float* enc_bhh  = (const float*)d_in[6];
    const float* dec_emb  = (const float*)d_in[7];
    const float* dec_Wih  = (const float*)d_in[8];
    const float* dec_Whh  = (const float*)d_in[9];
    const float* dec_bih  = (const float*)d_in[10];
    const float* dec_bhh  = (const float*)d_in[11];
    const float* dec_init = (const float*)d_in[12];
    const float* lin_W    = (const float*)d_in[13];
    const float* lin_b    = (const float*)d_in[14];
    float* out = (float*)d_out;

    float *gx, *ctxg, *hfin;
    int *didx, *bar;
    __nv_bfloat16 *pAh, *pAl, *pBh, *pBl, *weH, *weL, *wdH, *wdL;
    cudaGetSymbolAddress((void**)&gx, g_gx);
    cudaGetSymbolAddress((void**)&ctxg, g_ctxg);
    cudaGetSymbolAddress((void**)&hfin, g_hfin);
    cudaGetSymbolAddress((void**)&didx, g_didx);
    cudaGetSymbolAddress((void**)&bar, g_bar);
    cudaGetSymbolAddress((void**)&pAh, g_Ah);
    cudaGetSymbolAddress((void**)&pAl, g_Al);
    cudaGetSymbolAddress((void**)&pBh, g_Bh);
    cudaGetSymbolAddress((void**)&pBl, g_Bl);
    cudaGetSymbolAddress((void**)&weH, g_WencH);
    cudaGetSymbolAddress((void**)&weL, g_WencL);
    cudaGetSymbolAddress((void**)&wdH, g_WdecH);
    cudaGetSymbolAddress((void**)&wdL, g_WdecL);

    const int hmma_smem = 3 * STAGE_B;   // 96KB, 3-stage, 2 CTAs/SM
    cudaFuncSetAttribute(hmma_nt<512>,  cudaFuncAttributeMaxDynamicSharedMemorySize, hmma_smem);
    cudaFuncSetAttribute(hmma_nt<1024>, cudaFuncAttributeMaxDynamicSharedMemorySize, hmma_smem);
    cudaFuncSetAttribute(recur<false>, cudaFuncAttributeMaxDynamicSharedMemorySize, SMEM_REC);
    cudaFuncSetAttribute(recur<true>,  cudaFuncAttributeMaxDynamicSharedMemorySize, SMEM_REC);

    // one-time weight conversions
    whh_split<<<dim3(NCTA_R, NR), 256>>>(enc_Whh, weH, weL);
    whh_split<<<dim3(NCTA_R, NR), 256>>>(dec_Whh, wdH, wdL);

    // encoder input gates
    split_stride<<<G_, 128>>>(enc_Wih, E_, pBh, pBl, E_);
    gather_split<<<MT_, 128>>>(enc_emb, x, pAh, pAl);
    hmma_nt<512><<<dim3(MT_ / 128, G_ / 128), 256, hmma_smem>>>(
        pAh, pAl, pBh, pBl, enc_bih, gx, G_);

    // encoder recurrence
    cudaMemsetAsync(bar, 0, sizeof(int));
    recur<false><<<NCTA_R, 512, SMEM_REC>>>(weH, weL, gx, enc_bhh, nullptr, nullptr);

    // ctx gate contribution
    gemm64_nt<<<G_ / 32, 128>>>(hfin, H_, dec_Wih + E_, DI_, ctxg, G_, H_);

    // decoder input gates
    build_didx<<<MT_ / 256, 256>>>(labels);
    gather_split<<<MT_, 128>>>(dec_emb, didx, pAh, pAl);
    split_stride<<<G_, 128>>>(dec_Wih, DI_, pBh, pBl, E_);
    hmma_nt<512><<<dim3(MT_ / 128, G_ / 128), 256, hmma_smem>>>(
        pAh, pAl, pBh, pBl, dec_bih, gx, G_);

    // decoder recurrence
    cudaMemsetAsync(bar, 0, sizeof(int));
    recur<true><<<NCTA_R, 512, SMEM_REC>>>(wdH, wdL, gx, dec_bhh, ctxg, dec_init);

    // logits
    split_bf16<<<((int)((size_t)V_ * H_ / 4) + 255) / 256, 256>>>(
        lin_W, pBh, pBl, (int)((size_t)V_ * H_ / 4));
    hmma_nt<1024><<<dim3(MT_ / 128, V_ / 128), 256, hmma_smem>>>(
        pAh, pAl, pBh, pBl, lin_b, out, V_);
}